// round 12
// baseline (speedup 1.0000x reference)
#include <cuda_runtime.h>
#include <cuda_bf16.h>
#include <mma.h>
#include <cstdint>
#include <cstddef>

using namespace nvcuda;

// Problem dims (fixed by dataset)
#define NTC 400000
#define NMC 40000
#define CH  64
#define FT  384

// ---------------- scratch (static __device__ — no allocations) ----------------
__device__ float g_xt0[(size_t)NTC * CH];
__device__ float g_xt1[(size_t)NTC * CH];
__device__ float g_xt2[(size_t)NTC * CH];
__device__ float g_aggt[(size_t)NTC * CH];
__device__ float g_xm0[(size_t)NMC * CH];
__device__ float g_xm1[(size_t)NMC * CH];
__device__ float g_xm2[(size_t)NMC * CH];
__device__ float g_aggm[(size_t)NMC * CH];
__device__ float g_ym[(size_t)NMC * CH];
__device__ int   g_cnt_t[NTC];
__device__ int   g_cnt_m[NMC];
__device__ float g_inv_t[NTC];
__device__ float g_inv_m[NMC];

// ---------------- packed f32x2 FMA ----------------
union F2U { float2 f; unsigned long long u; };
__device__ __forceinline__ float2 ffma2(float2 a, float2 b, float2 c) {
    F2U A, B, Cc, D;
    A.f = a; B.f = b; Cc.f = c;
    asm("fma.rn.f32x2 %0, %1, %2, %3;" : "=l"(D.u) : "l"(A.u), "l"(B.u), "l"(Cc.u));
    return D.f;
}

// ---------------- degree / recip ----------------
__global__ void degree_kernel(const int* __restrict__ esrc, const int* __restrict__ edst, int E) {
    int t = blockIdx.x * blockDim.x + threadIdx.x;
    if (t < E) {
        atomicAdd(&g_cnt_t[esrc[t]], 1);
        atomicAdd(&g_cnt_m[edst[t]], 1);
    }
}

__global__ void recip_kernel(const int* __restrict__ cnt, float* __restrict__ inv, int n) {
    int t = blockIdx.x * blockDim.x + threadIdx.x;
    if (t < n) inv[t] = 1.0f / fmaxf((float)cnt[t], 1.0f);
}

// ---------------- mentor encoder: x_m0 = emb_m[mentor_id] ----------------
__global__ void gather_rows_kernel(const float* __restrict__ src, const int* __restrict__ ids,
                                   float* __restrict__ out, int n) {
    int t = blockIdx.x * blockDim.x + threadIdx.x;
    int e = t >> 4;
    if (e >= n) return;
    int c4 = (t & 15) << 2;
    int id = __ldg(&ids[e]);
    float4 v = *reinterpret_cast<const float4*>(&src[(size_t)id * CH + c4]);
    *reinterpret_cast<float4*>(&out[(size_t)e * CH + c4]) = v;
}

// ---------------- edge scatter-add ----------------
__global__ void scatter_kernel(const float* __restrict__ feat, const int* __restrict__ gidx,
                               const int* __restrict__ sidx, float* __restrict__ agg, int E) {
    int t = blockIdx.x * blockDim.x + threadIdx.x;
    int e = t >> 4;
    if (e >= E) return;
    int c4 = (t & 15) << 2;
    int s = __ldg(&gidx[e]);
    int d = __ldg(&sidx[e]);
    float4 v = *reinterpret_cast<const float4*>(&feat[(size_t)s * CH + c4]);
    float* p = &agg[(size_t)d * CH + c4];
    asm volatile("red.global.add.v4.f32 [%0], {%1, %2, %3, %4};"
                 :: "l"(p), "f"(v.x), "f"(v.y), "f"(v.z), "f"(v.w) : "memory");
}

// ============================================================================
// Shared wmma bf16-split machinery — 4-warp variant (warp tile 32 rows x 64 cols)
// ============================================================================
#define AST 40   // smem k-stride (elements), mult of 8 for wmma ldm

struct CvBufs {
    __nv_bfloat16 Ahi[128][AST];
    __nv_bfloat16 Alo[128][AST];
    __nv_bfloat16 Bhi[64][AST];
    __nv_bfloat16 Blo[64][AST];
};

struct WSmem {
    union {
        CvBufs cv;
        float C[128][68];
    } u;
};

__device__ __forceinline__ void cvt_store_split(__nv_bfloat16* hi_p, __nv_bfloat16* lo_p,
                                                float4 v) {
    __nv_bfloat162 h01 = __floats2bfloat162_rn(v.x, v.y);
    __nv_bfloat162 h23 = __floats2bfloat162_rn(v.z, v.w);
    float2 f01 = __bfloat1622float2(h01);
    float2 f23 = __bfloat1622float2(h23);
    __nv_bfloat162 l01 = __floats2bfloat162_rn(v.x - f01.x, v.y - f01.y);
    __nv_bfloat162 l23 = __floats2bfloat162_rn(v.z - f23.x, v.w - f23.y);
    *reinterpret_cast<uint2*>(hi_p) = make_uint2(
        *reinterpret_cast<uint32_t*>(&h01), *reinterpret_cast<uint32_t*>(&h23));
    *reinterpret_cast<uint2*>(lo_p) = make_uint2(
        *reinterpret_cast<uint32_t*>(&l01), *reinterpret_cast<uint32_t*>(&l23));
}

// warp computes 32x64 tile: 2x4 accumulators, 3 split terms per 16-k step.
// B fragments loaded inside the j loop to bound register pressure.
__device__ __forceinline__ void wmma_chunk_mma4(
    CvBufs& cv, int warp_r,
    wmma::fragment<wmma::accumulator, 16, 16, 16, float> (&acc)[2][4]) {
#pragma unroll
    for (int kk = 0; kk < 32; kk += 16) {
        wmma::fragment<wmma::matrix_a, 16, 16, 16, __nv_bfloat16, wmma::row_major> ah[2], al[2];
#pragma unroll
        for (int i = 0; i < 2; i++) {
            wmma::load_matrix_sync(ah[i], &cv.Ahi[warp_r * 32 + i * 16][kk], AST);
            wmma::load_matrix_sync(al[i], &cv.Alo[warp_r * 32 + i * 16][kk], AST);
        }
#pragma unroll
        for (int j = 0; j < 4; j++) {
            wmma::fragment<wmma::matrix_b, 16, 16, 16, __nv_bfloat16, wmma::col_major> bh, bl;
            wmma::load_matrix_sync(bh, &cv.Bhi[j * 16][kk], AST);
            wmma::load_matrix_sync(bl, &cv.Blo[j * 16][kk], AST);
#pragma unroll
            for (int i = 0; i < 2; i++) {
                wmma::mma_sync(acc[i][j], ah[i], bh, acc[i][j]);
                wmma::mma_sync(acc[i][j], ah[i], bl, acc[i][j]);
                wmma::mma_sync(acc[i][j], al[i], bh, acc[i][j]);
            }
        }
    }
}

// ============================================================================
// wmma encoder (128 threads, 4 warps): out[128,64] = X[128,384]@W[64,384]^T+b+emb
// ============================================================================
__global__ __launch_bounds__(128, 4)
void encoder_wmma_kernel(const float* __restrict__ X, const float* __restrict__ W,
                         const float* __restrict__ bias, const float* __restrict__ emb,
                         const int* __restrict__ ids, float* __restrict__ out) {
    __shared__ WSmem sm;
    int tid = threadIdx.x;
    int warp_r = tid >> 5;
    int row0 = blockIdx.x * 128;

    wmma::fragment<wmma::accumulator, 16, 16, 16, float> acc[2][4];
#pragma unroll
    for (int i = 0; i < 2; i++)
#pragma unroll
        for (int j = 0; j < 4; j++) wmma::fill_fragment(acc[i][j], 0.0f);

    for (int ch = 0; ch < FT / 32; ch++) {
        int kt = ch * 32;
        // A chunk 128x32: 8 float4 per thread
#pragma unroll
        for (int j = 0; j < 8; j++) {
            int idx = tid + 128 * j;
            int r = idx >> 3, cq = (idx & 7) << 2;
            float4 v = *reinterpret_cast<const float4*>(&X[(size_t)(row0 + r) * FT + kt + cq]);
            cvt_store_split(&sm.u.cv.Ahi[r][cq], &sm.u.cv.Alo[r][cq], v);
        }
        // W chunk 64x32: 4 float4 per thread
#pragma unroll
        for (int j = 0; j < 4; j++) {
            int idx = tid + 128 * j;
            int r = idx >> 3, cq = (idx & 7) << 2;
            float4 v = *reinterpret_cast<const float4*>(&W[(size_t)r * FT + kt + cq]);
            cvt_store_split(&sm.u.cv.Bhi[r][cq], &sm.u.cv.Blo[r][cq], v);
        }
        __syncthreads();
        wmma_chunk_mma4(sm.u.cv, warp_r, acc);
        __syncthreads();
    }

#pragma unroll
    for (int i = 0; i < 2; i++)
#pragma unroll
        for (int j = 0; j < 4; j++)
            wmma::store_matrix_sync(&sm.u.C[warp_r * 32 + i * 16][j * 16],
                                    acc[i][j], 68, wmma::mem_row_major);
    __syncthreads();

    int tx = tid & 15, ty = tid >> 4;   // ty 0..7
    int c4 = tx * 4;
    float4 bv = *reinterpret_cast<const float4*>(&bias[c4]);
#pragma unroll
    for (int p = 0; p < 16; p++) {
        int r = ty + p * 8;
        int nid = __ldg(&ids[row0 + r]);
        float4 ev = *reinterpret_cast<const float4*>(&emb[(size_t)nid * CH + c4]);
        float4 o;
        o.x = sm.u.C[r][c4 + 0] + bv.x + ev.x;
        o.y = sm.u.C[r][c4 + 1] + bv.y + ev.y;
        o.z = sm.u.C[r][c4 + 2] + bv.z + ev.z;
        o.w = sm.u.C[r][c4 + 3] + bv.w + ev.w;
        *reinterpret_cast<float4*>(&out[(size_t)(row0 + r) * CH + c4]) = o;
    }
}

// ============================================================================
// wmma thesis-SAGE GEMM (128 threads, 4 warps):
// out[128,64] = act( X[128,64]@W[64,64]^T + agg*inv + b )
// ============================================================================
template <bool RELU>
__global__ __launch_bounds__(128, 4)
void gemm64_wmma_kernel(const float* __restrict__ X, const float* __restrict__ W,
                        const float* __restrict__ bias,
                        const float* __restrict__ aggY, const float* __restrict__ inv,
                        float* __restrict__ out) {
    __shared__ WSmem sm;
    int tid = threadIdx.x;
    int warp_r = tid >> 5;
    int row0 = blockIdx.x * 128;

    wmma::fragment<wmma::accumulator, 16, 16, 16, float> acc[2][4];
#pragma unroll
    for (int i = 0; i < 2; i++)
#pragma unroll
        for (int j = 0; j < 4; j++) wmma::fill_fragment(acc[i][j], 0.0f);

#pragma unroll
    for (int ch = 0; ch < 2; ch++) {
        int kt = ch * 32;
#pragma unroll
        for (int j = 0; j < 8; j++) {
            int idx = tid + 128 * j;
            int r = idx >> 3, cq = (idx & 7) << 2;
            float4 v = *reinterpret_cast<const float4*>(&X[(size_t)(row0 + r) * CH + kt + cq]);
            cvt_store_split(&sm.u.cv.Ahi[r][cq], &sm.u.cv.Alo[r][cq], v);
        }
#pragma unroll
        for (int j = 0; j < 4; j++) {
            int idx = tid + 128 * j;
            int r = idx >> 3, cq = (idx & 7) << 2;
            float4 v = *reinterpret_cast<const float4*>(&W[(size_t)r * CH + kt + cq]);
            cvt_store_split(&sm.u.cv.Bhi[r][cq], &sm.u.cv.Blo[r][cq], v);
        }
        __syncthreads();
        wmma_chunk_mma4(sm.u.cv, warp_r, acc);
        __syncthreads();
    }

#pragma unroll
    for (int i = 0; i < 2; i++)
#pragma unroll
        for (int j = 0; j < 4; j++)
            wmma::store_matrix_sync(&sm.u.C[warp_r * 32 + i * 16][j * 16],
                                    acc[i][j], 68, wmma::mem_row_major);
    __syncthreads();

    int tx = tid & 15, ty = tid >> 4;
    int c4 = tx * 4;
    float4 bv = *reinterpret_cast<const float4*>(&bias[c4]);
#pragma unroll
    for (int p = 0; p < 16; p++) {
        int r = ty + p * 8;
        int gr = row0 + r;
        float sc = __ldg(&inv[gr]);
        float4 av = *reinterpret_cast<const float4*>(&aggY[(size_t)gr * CH + c4]);
        float4 o;
        o.x = fmaf(av.x, sc, sm.u.C[r][c4 + 0] + bv.x);
        o.y = fmaf(av.y, sc, sm.u.C[r][c4 + 1] + bv.y);
        o.z = fmaf(av.z, sc, sm.u.C[r][c4 + 2] + bv.z);
        o.w = fmaf(av.w, sc, sm.u.C[r][c4 + 3] + bv.w);
        if (RELU) {
            o.x = fmaxf(o.x, 0.f); o.y = fmaxf(o.y, 0.f);
            o.z = fmaxf(o.z, 0.f); o.w = fmaxf(o.w, 0.f);
        }
        *reinterpret_cast<float4*>(&out[(size_t)gr * CH + c4]) = o;
    }
}

// ---------------- K=64 FFMA2 GEMM (mentor-side, R4 proven body) ----------------
template <bool RELU, bool BIAS, bool ADDAGG>
__global__ __launch_bounds__(256)
void gemm64_kernel(const float* __restrict__ X, const float* __restrict__ W,
                   const float* __restrict__ bias,
                   const float* __restrict__ aggY, const float* __restrict__ inv,
                   float* __restrict__ out, int M) {
    __shared__ float As[32][132];
    __shared__ float Ws[32][68];
    int tid = threadIdx.x;
    int tx = tid & 15, ty = tid >> 4;
    int row0 = blockIdx.x * 128;

    float2 acc[4][4];
#pragma unroll
    for (int i = 0; i < 4; i++)
#pragma unroll
        for (int j = 0; j < 4; j++) acc[i][j] = make_float2(0.f, 0.f);

    for (int kt = 0; kt < CH; kt += 32) {
#pragma unroll
        for (int i = 0; i < 4; i++) {
            int idx = tid + 256 * i;
            int r = idx >> 3;
            int kq = (idx & 7) << 2;
            int grow = row0 + r;
            float4 v = make_float4(0.f, 0.f, 0.f, 0.f);
            if (grow < M)
                v = *reinterpret_cast<const float4*>(&X[(size_t)grow * CH + kt + kq]);
            As[kq + 0][r] = v.x; As[kq + 1][r] = v.y;
            As[kq + 2][r] = v.z; As[kq + 3][r] = v.w;
        }
#pragma unroll
        for (int i = 0; i < 2; i++) {
            int idx = tid + 256 * i;
            int c = idx >> 3;
            int kq = (idx & 7) << 2;
            float4 v = *reinterpret_cast<const float4*>(&W[(size_t)c * CH + kt + kq]);
            Ws[kq + 0][c] = v.x; Ws[kq + 1][c] = v.y;
            Ws[kq + 2][c] = v.z; Ws[kq + 3][c] = v.w;
        }
        __syncthreads();
#pragma unroll
        for (int k = 0; k < 32; k++) {
            float4 a0 = *reinterpret_cast<const float4*>(&As[k][ty * 8]);
            float4 a1 = *reinterpret_cast<const float4*>(&As[k][ty * 8 + 4]);
            float4 w  = *reinterpret_cast<const float4*>(&Ws[k][tx * 4]);
            float2 ap[4] = { {a0.x, a0.y}, {a0.z, a0.w}, {a1.x, a1.y}, {a1.z, a1.w} };
            float2 wd[4] = { {w.x, w.x}, {w.y, w.y}, {w.z, w.z}, {w.w, w.w} };
#pragma unroll
            for (int rp = 0; rp < 4; rp++)
#pragma unroll
                for (int j = 0; j < 4; j++)
                    acc[rp][j] = ffma2(ap[rp], wd[j], acc[rp][j]);
        }
        __syncthreads();
    }

    float4 bv = make_float4(0.f, 0.f, 0.f, 0.f);
    if (BIAS) bv = *reinterpret_cast<const float4*>(&bias[tx * 4]);
#pragma unroll
    for (int rp = 0; rp < 4; rp++) {
#pragma unroll
        for (int s = 0; s < 2; s++) {
            int r = row0 + ty * 8 + rp * 2 + s;
            if (r < M) {
                float4 o;
                o.x = (s ? acc[rp][0].y : acc[rp][0].x) + bv.x;
                o.y = (s ? acc[rp][1].y : acc[rp][1].x) + bv.y;
                o.z = (s ? acc[rp][2].y : acc[rp][2].x) + bv.z;
                o.w = (s ? acc[rp][3].y : acc[rp][3].x) + bv.w;
                if (ADDAGG) {
                    float sc = __ldg(&inv[r]);
                    float4 av = *reinterpret_cast<const float4*>(&aggY[(size_t)r * CH + tx * 4]);
                    o.x = fmaf(av.x, sc, o.x);
                    o.y = fmaf(av.y, sc, o.y);
                    o.z = fmaf(av.z, sc, o.z);
                    o.w = fmaf(av.w, sc, o.w);
                }
                if (RELU) {
                    o.x = fmaxf(o.x, 0.f); o.y = fmaxf(o.y, 0.f);
                    o.z = fmaxf(o.z, 0.f); o.w = fmaxf(o.w, 0.f);
                }
                *reinterpret_cast<float4*>(&out[(size_t)r * CH + tx * 4]) = o;
            }
        }
    }
}

// ---------------- mentor SAGE layer GEMM (K=128, R4 proven body) ---------------
template <bool RELU>
__global__ __launch_bounds__(256)
void sage_kernel(const float* __restrict__ Agg, const float* __restrict__ inv,
                 const float* __restrict__ Xs,
                 const float* __restrict__ Wl, const float* __restrict__ Wr,
                 const float* __restrict__ bias, float* __restrict__ out, int M) {
    __shared__ float As[32][132];
    __shared__ float Ws[32][68];
    int tid = threadIdx.x;
    int tx = tid & 15, ty = tid >> 4;
    int row0 = blockIdx.x * 128;

    float2 acc[4][4];
#pragma unroll
    for (int i = 0; i < 4; i++)
#pragma unroll
        for (int j = 0; j < 4; j++) acc[i][j] = make_float2(0.f, 0.f);

    for (int tt = 0; tt < 4; tt++) {
        const float* A  = (tt < 2) ? Agg : Xs;
        const float* Wp = (tt < 2) ? Wl  : Wr;
        bool do_scale = (tt < 2);
        int kt = (tt & 1) * 32;
#pragma unroll
        for (int i = 0; i < 4; i++) {
            int idx = tid + 256 * i;
            int r = idx >> 3;
            int kq = (idx & 7) << 2;
            int grow = row0 + r;
            float4 v = make_float4(0.f, 0.f, 0.f, 0.f);
            if (grow < M) {
                v = *reinterpret_cast<const float4*>(&A[(size_t)grow * CH + kt + kq]);
                if (do_scale) {
                    float sc = __ldg(&inv[grow]);
                    v.x *= sc; v.y *= sc; v.z *= sc; v.w *= sc;
                }
            }
            As[kq + 0][r] = v.x; As[kq + 1][r] = v.y;
            As[kq + 2][r] = v.z; As[kq + 3][r] = v.w;
        }
#pragma unroll
        for (int i = 0; i < 2; i++) {
            int idx = tid + 256 * i;
            int c = idx >> 3;
            int kq = (idx & 7) << 2;
            float4 v = *reinterpret_cast<const float4*>(&Wp[(size_t)c * CH + kt + kq]);
            Ws[kq + 0][c] = v.x; Ws[kq + 1][c] = v.y;
            Ws[kq + 2][c] = v.z; Ws[kq + 3][c] = v.w;
        }
        __syncthreads();
#pragma unroll
        for (int k = 0; k < 32; k++) {
            float4 a0 = *reinterpret_cast<const float4*>(&As[k][ty * 8]);
            float4 a1 = *reinterpret_cast<const float4*>(&As[k][ty * 8 + 4]);
            float4 w  = *reinterpret_cast<const float4*>(&Ws[k][tx * 4]);
            float2 ap[4] = { {a0.x, a0.y}, {a0.z, a0.w}, {a1.x, a1.y}, {a1.z, a1.w} };
            float2 wd[4] = { {w.x, w.x}, {w.y, w.y}, {w.z, w.z}, {w.w, w.w} };
#pragma unroll
            for (int rp = 0; rp < 4; rp++)
#pragma unroll
                for (int j = 0; j < 4; j++)
                    acc[rp][j] = ffma2(ap[rp], wd[j], acc[rp][j]);
        }
        __syncthreads();
    }

    float4 bv = *reinterpret_cast<const float4*>(&bias[tx * 4]);
#pragma unroll
    for (int rp = 0; rp < 4; rp++) {
#pragma unroll
        for (int s = 0; s < 2; s++) {
            int r = row0 + ty * 8 + rp * 2 + s;
            if (r < M) {
                float4 o;
                o.x = (s ? acc[rp][0].y : acc[rp][0].x) + bv.x;
                o.y = (s ? acc[rp][1].y : acc[rp][1].x) + bv.y;
                o.z = (s ? acc[rp][2].y : acc[rp][2].x) + bv.z;
                o.w = (s ? acc[rp][3].y : acc[rp][3].x) + bv.w;
                if (RELU) {
                    o.x = fmaxf(o.x, 0.f); o.y = fmaxf(o.y, 0.f);
                    o.z = fmaxf(o.z, 0.f); o.w = fmaxf(o.w, 0.f);
                }
                *reinterpret_cast<float4*>(&out[(size_t)r * CH + tx * 4]) = o;
            }
        }
    }
}

// ---------------- edge dot-product classifier --------------------------------
__global__ void edge_dot_kernel(const float* __restrict__ xt, const float* __restrict__ xm,
                                const int* __restrict__ es, const int* __restrict__ ed,
                                float* __restrict__ out, int E) {
    int t = blockIdx.x * blockDim.x + threadIdx.x;
    int e = t >> 4;
    if (e >= E) return;
    int c4 = (t & 15) << 2;
    int s = __ldg(&es[e]);
    int d = __ldg(&ed[e]);
    float4 a = *reinterpret_cast<const float4*>(&xt[(size_t)s * CH + c4]);
    float4 b = *reinterpret_cast<const float4*>(&xm[(size_t)d * CH + c4]);
    float p = a.x * b.x + a.y * b.y + a.z * b.z + a.w * b.w;
    p += __shfl_down_sync(0xffffffffu, p, 8);
    p += __shfl_down_sync(0xffffffffu, p, 4);
    p += __shfl_down_sync(0xffffffffu, p, 2);
    p += __shfl_down_sync(0xffffffffu, p, 1);
    if ((t & 15) == 0) out[e] = p;
}

// ---------------- launch -----------------------------------------------------
extern "C" void kernel_launch(void* const* d_in, const int* in_sizes, int n_in,
                              void* d_out, int out_size) {
    const float* x_thesis  = (const float*)d_in[0];
    const int*   thesis_id = (const int*)d_in[1];
    const int*   mentor_id = (const int*)d_in[2];
    const int*   edge_src  = (const int*)d_in[3];
    const int*   edge_dst  = (const int*)d_in[4];
    const int*   el_src    = (const int*)d_in[5];
    const int*   el_dst    = (const int*)d_in[6];
    const float* lin_W     = (const float*)d_in[7];
    const float* lin_b     = (const float*)d_in[8];
    const float* emb_t     = (const float*)d_in[9];
    const float* emb_m     = (const float*)d_in[10];
    const float* Wl_tm0    = (const float*)d_in[11];
    const float* Wr_tm0    = (const float*)d_in[12];
    const float* b_tm0     = (const float*)d_in[13];
    const float* Wl_mt0    = (const float*)d_in[14];
    const float* Wr_mt0    = (const float*)d_in[15];
    const float* b_mt0     = (const float*)d_in[16];
    const float* Wl_tm1    = (const float*)d_in[17];
    const float* Wr_tm1    = (const float*)d_in[18];
    const float* b_tm1     = (const float*)d_in[19];
    const float* Wl_mt1    = (const float*)d_in[20];
    const float* Wr_mt1    = (const float*)d_in[21];
    const float* b_mt1     = (const float*)d_in[22];
    float* out = (float*)d_out;

    int nt = in_sizes[1];
    int nm = in_sizes[2];
    int E  = in_sizes[3];
    int EL = in_sizes[5];

    void *p_xt0, *p_xt1, *p_xt2, *p_aggt, *p_xm0, *p_xm1, *p_xm2, *p_aggm, *p_ym;
    void *p_cntt, *p_cntm, *p_invt, *p_invm;
    cudaGetSymbolAddress(&p_xt0, g_xt0);   cudaGetSymbolAddress(&p_xt1, g_xt1);
    cudaGetSymbolAddress(&p_xt2, g_xt2);   cudaGetSymbolAddress(&p_aggt, g_aggt);
    cudaGetSymbolAddress(&p_xm0, g_xm0);   cudaGetSymbolAddress(&p_xm1, g_xm1);
    cudaGetSymbolAddress(&p_xm2, g_xm2);   cudaGetSymbolAddress(&p_aggm, g_aggm);
    cudaGetSymbolAddress(&p_ym, g_ym);
    cudaGetSymbolAddress(&p_cntt, g_cnt_t); cudaGetSymbolAddress(&p_cntm, g_cnt_m);
    cudaGetSymbolAddress(&p_invt, g_inv_t); cudaGetSymbolAddress(&p_invm, g_inv_m);

    float* xt0 = (float*)p_xt0; float* xt1 = (float*)p_xt1; float* xt2 = (float*)p_xt2;
    float* aggt = (float*)p_aggt;
    float* xm0 = (float*)p_xm0; float* xm1 = (float*)p_xm1; float* xm2 = (float*)p_xm2;
    float* aggm = (float*)p_aggm; float* ym = (float*)p_ym;
    int* cntt = (int*)p_cntt; int* cntm = (int*)p_cntm;
    float* invt = (float*)p_invt; float* invm = (float*)p_invm;

    const int TB = 256;
    int gridE16  = (E * 16 + TB - 1) / TB;
    int gridEL16 = (EL * 16 + TB - 1) / TB;
    int gridNT   = (nt + 127) / 128;
    int gridNM   = (nm + 127) / 128;

    // ---- exactly 5 launches before the encoder so ncu (-s 5 -c 1) captures it --
    cudaMemsetAsync(cntt, 0, (size_t)nt * sizeof(int));
    cudaMemsetAsync(cntm, 0, (size_t)nm * sizeof(int));
    degree_kernel<<<(E + TB - 1) / TB, TB>>>(edge_src, edge_dst, E);
    recip_kernel<<<(nt + TB - 1) / TB, TB>>>(cntt, invt, nt);
    recip_kernel<<<(nm + TB - 1) / TB, TB>>>(cntm, invm, nm);

    encoder_wmma_kernel<<<gridNT, 128>>>(x_thesis, lin_W, lin_b, emb_t, thesis_id, xt0);
    gather_rows_kernel<<<(nm * 16 + TB - 1) / TB, TB>>>(emb_m, mentor_id, xm0, nm);

    // ---- layer 0 ----
    gemm64_kernel<false, false, false><<<gridNM, TB>>>(xm0, Wl_mt0, nullptr, nullptr, nullptr, ym, nm);
    cudaMemsetAsync(aggm, 0, (size_t)nm * CH * sizeof(float));
    cudaMemsetAsync(aggt, 0, (size_t)nt * CH * sizeof(float));
    scatter_kernel<<<gridE16, TB>>>(xt0, edge_src, edge_dst, aggm, E);
    scatter_kernel<<<gridE16, TB>>>(ym, edge_dst, edge_src, aggt, E);
    sage_kernel<true><<<gridNM, TB>>>(aggm, invm, xm0, Wl_tm0, Wr_tm0, b_tm0, xm1, nm);
    gemm64_wmma_kernel<true><<<gridNT, 128>>>(xt0, Wr_mt0, b_mt0, aggt, invt, xt1);

    // ---- layer 1 ----
    gemm64_kernel<false, false, false><<<gridNM, TB>>>(xm1, Wl_mt1, nullptr, nullptr, nullptr, ym, nm);
    cudaMemsetAsync(aggm, 0, (size_t)nm * CH * sizeof(float));
    cudaMemsetAsync(aggt, 0, (size_t)nt * CH * sizeof(float));
    scatter_kernel<<<gridE16, TB>>>(xt1, edge_src, edge_dst, aggm, E);
    scatter_kernel<<<gridE16, TB>>>(ym, edge_dst, edge_src, aggt, E);
    sage_kernel<false><<<gridNM, TB>>>(aggm, invm, xm1, Wl_tm1, Wr_tm1, b_tm1, xm2, nm);
    gemm64_wmma_kernel<false><<<gridNT, 128>>>(xt1, Wr_mt1, b_mt1, aggt, invt, xt2);

    // classifier
    edge_dot_kernel<<<gridEL16, TB>>>(xt2, xm2, el_src, el_dst, out, EL);
}

// round 13
// speedup vs baseline: 1.0945x; 1.0945x over previous
#include <cuda_runtime.h>
#include <cuda_bf16.h>
#include <mma.h>
#include <cstdint>
#include <cstddef>

using namespace nvcuda;

// Problem dims (fixed by dataset)
#define NTC 400000
#define NMC 40000
#define CH  64
#define FT  384

// ---------------- scratch (static __device__ — no allocations) ----------------
__device__ float g_xt0[(size_t)NTC * CH];
__device__ float g_xt1[(size_t)NTC * CH];
__device__ float g_xt2[(size_t)NTC * CH];
__device__ float g_aggt[(size_t)NTC * CH];
__device__ float g_xm0[(size_t)NMC * CH];
__device__ float g_xm1[(size_t)NMC * CH];
__device__ float g_xm2[(size_t)NMC * CH];
__device__ float g_aggm[(size_t)NMC * CH];
__device__ float g_ym[(size_t)NMC * CH];
__device__ int   g_cnt_t[NTC];
__device__ int   g_cnt_m[NMC];
__device__ float g_inv_t[NTC];
__device__ float g_inv_m[NMC];

// ---------------- packed f32x2 FMA ----------------
union F2U { float2 f; unsigned long long u; };
__device__ __forceinline__ float2 ffma2(float2 a, float2 b, float2 c) {
    F2U A, B, Cc, D;
    A.f = a; B.f = b; Cc.f = c;
    asm("fma.rn.f32x2 %0, %1, %2, %3;" : "=l"(D.u) : "l"(A.u), "l"(B.u), "l"(Cc.u));
    return D.f;
}

// ---------------- degree / recip ----------------
__global__ void degree_kernel(const int* __restrict__ esrc, const int* __restrict__ edst, int E) {
    int t = blockIdx.x * blockDim.x + threadIdx.x;
    if (t < E) {
        atomicAdd(&g_cnt_t[esrc[t]], 1);
        atomicAdd(&g_cnt_m[edst[t]], 1);
    }
}

__global__ void recip_kernel(const int* __restrict__ cnt, float* __restrict__ inv, int n) {
    int t = blockIdx.x * blockDim.x + threadIdx.x;
    if (t < n) inv[t] = 1.0f / fmaxf((float)cnt[t], 1.0f);
}

// ---------------- mentor encoder: x_m0 = emb_m[mentor_id] ----------------
__global__ void gather_rows_kernel(const float* __restrict__ src, const int* __restrict__ ids,
                                   float* __restrict__ out, int n) {
    int t = blockIdx.x * blockDim.x + threadIdx.x;
    int e = t >> 4;
    if (e >= n) return;
    int c4 = (t & 15) << 2;
    int id = __ldg(&ids[e]);
    float4 v = *reinterpret_cast<const float4*>(&src[(size_t)id * CH + c4]);
    *reinterpret_cast<float4*>(&out[(size_t)e * CH + c4]) = v;
}

// ---------------- edge scatter-add ----------------
__global__ void scatter_kernel(const float* __restrict__ feat, const int* __restrict__ gidx,
                               const int* __restrict__ sidx, float* __restrict__ agg, int E) {
    int t = blockIdx.x * blockDim.x + threadIdx.x;
    int e = t >> 4;
    if (e >= E) return;
    int c4 = (t & 15) << 2;
    int s = __ldg(&gidx[e]);
    int d = __ldg(&sidx[e]);
    float4 v = *reinterpret_cast<const float4*>(&feat[(size_t)s * CH + c4]);
    float* p = &agg[(size_t)d * CH + c4];
    asm volatile("red.global.add.v4.f32 [%0], {%1, %2, %3, %4};"
                 :: "l"(p), "f"(v.x), "f"(v.y), "f"(v.z), "f"(v.w) : "memory");
}

// ============================================================================
// wmma bf16-split machinery — 4 warps, warp tile 32x64, double-buffered cv
// ============================================================================
#define AST 40   // smem k-stride (elements), mult of 8 for wmma ldm

struct CvBufs {
    __nv_bfloat16 Ahi[128][AST];
    __nv_bfloat16 Alo[128][AST];
    __nv_bfloat16 Bhi[64][AST];
    __nv_bfloat16 Blo[64][AST];
};

struct PipeSmem {
    union {
        CvBufs cv[2];
        float C[128][68];
    } u;
};
#define PIPE_SMEM ((int)sizeof(PipeSmem))

__device__ __forceinline__ void cvt_store_split(__nv_bfloat16* hi_p, __nv_bfloat16* lo_p,
                                                float4 v) {
    __nv_bfloat162 h01 = __floats2bfloat162_rn(v.x, v.y);
    __nv_bfloat162 h23 = __floats2bfloat162_rn(v.z, v.w);
    float2 f01 = __bfloat1622float2(h01);
    float2 f23 = __bfloat1622float2(h23);
    __nv_bfloat162 l01 = __floats2bfloat162_rn(v.x - f01.x, v.y - f01.y);
    __nv_bfloat162 l23 = __floats2bfloat162_rn(v.z - f23.x, v.w - f23.y);
    *reinterpret_cast<uint2*>(hi_p) = make_uint2(
        *reinterpret_cast<uint32_t*>(&h01), *reinterpret_cast<uint32_t*>(&h23));
    *reinterpret_cast<uint2*>(lo_p) = make_uint2(
        *reinterpret_cast<uint32_t*>(&l01), *reinterpret_cast<uint32_t*>(&l23));
}

// convert staged regs into cv buffer (A: 8 f4/thread, B: 4 f4/thread, 128 thr)
__device__ __forceinline__ void convert_chunk(CvBufs& cv, int tid,
                                              const float4 (&ar)[8], const float4 (&wr)[4]) {
#pragma unroll
    for (int j = 0; j < 8; j++) {
        int idx = tid + 128 * j;
        int r = idx >> 3, cq = (idx & 7) << 2;
        cvt_store_split(&cv.Ahi[r][cq], &cv.Alo[r][cq], ar[j]);
    }
#pragma unroll
    for (int j = 0; j < 4; j++) {
        int idx = tid + 128 * j;
        int r = idx >> 3, cq = (idx & 7) << 2;
        cvt_store_split(&cv.Bhi[r][cq], &cv.Blo[r][cq], wr[j]);
    }
}

// warp computes 32x64 tile: 2x4 accumulators, 3 split terms per 16-k step
__device__ __forceinline__ void wmma_chunk_mma4(
    CvBufs& cv, int warp_r,
    wmma::fragment<wmma::accumulator, 16, 16, 16, float> (&acc)[2][4]) {
#pragma unroll
    for (int kk = 0; kk < 32; kk += 16) {
        wmma::fragment<wmma::matrix_a, 16, 16, 16, __nv_bfloat16, wmma::row_major> ah[2], al[2];
#pragma unroll
        for (int i = 0; i < 2; i++) {
            wmma::load_matrix_sync(ah[i], &cv.Ahi[warp_r * 32 + i * 16][kk], AST);
            wmma::load_matrix_sync(al[i], &cv.Alo[warp_r * 32 + i * 16][kk], AST);
        }
#pragma unroll
        for (int j = 0; j < 4; j++) {
            wmma::fragment<wmma::matrix_b, 16, 16, 16, __nv_bfloat16, wmma::col_major> bh, bl;
            wmma::load_matrix_sync(bh, &cv.Bhi[j * 16][kk], AST);
            wmma::load_matrix_sync(bl, &cv.Blo[j * 16][kk], AST);
#pragma unroll
            for (int i = 0; i < 2; i++) {
                wmma::mma_sync(acc[i][j], ah[i], bh, acc[i][j]);
                wmma::mma_sync(acc[i][j], ah[i], bl, acc[i][j]);
                wmma::mma_sync(acc[i][j], al[i], bh, acc[i][j]);
            }
        }
    }
}

// ============================================================================
// Pipelined wmma encoder (128 thr): out[128,64] = X[128,384]@W[64,384]^T+b+emb
// ============================================================================
__global__ __launch_bounds__(128, 3)
void encoder_wmma_kernel(const float* __restrict__ X, const float* __restrict__ W,
                         const float* __restrict__ bias, const float* __restrict__ emb,
                         const int* __restrict__ ids, float* __restrict__ out) {
    extern __shared__ char smraw[];
    PipeSmem& sm = *reinterpret_cast<PipeSmem*>(smraw);
    int tid = threadIdx.x;
    int warp_r = tid >> 5;
    int row0 = blockIdx.x * 128;

    wmma::fragment<wmma::accumulator, 16, 16, 16, float> acc[2][4];
#pragma unroll
    for (int i = 0; i < 2; i++)
#pragma unroll
        for (int j = 0; j < 4; j++) wmma::fill_fragment(acc[i][j], 0.0f);

    int a_r = tid >> 3;               // 0..15 base row (strides of 16)
    int cq  = (tid & 7) << 2;
    float4 ar[8], wr[4];

    // ---- chunk 0: load + convert ----
#pragma unroll
    for (int j = 0; j < 8; j++)
        ar[j] = *reinterpret_cast<const float4*>(&X[(size_t)(row0 + a_r + 16 * j) * FT + cq]);
#pragma unroll
    for (int j = 0; j < 4; j++)
        wr[j] = *reinterpret_cast<const float4*>(&W[(size_t)(a_r + 16 * j) * FT + cq]);
    convert_chunk(sm.u.cv[0], tid, ar, wr);
    __syncthreads();

    const int NC = FT / 32;  // 12
    for (int ch = 0; ch < NC; ch++) {
        int buf = ch & 1;
        bool more = (ch + 1 < NC);
        if (more) {
            int kt = (ch + 1) * 32;
#pragma unroll
            for (int j = 0; j < 8; j++)
                ar[j] = *reinterpret_cast<const float4*>(
                    &X[(size_t)(row0 + a_r + 16 * j) * FT + kt + cq]);
#pragma unroll
            for (int j = 0; j < 4; j++)
                wr[j] = *reinterpret_cast<const float4*>(
                    &W[(size_t)(a_r + 16 * j) * FT + kt + cq]);
        }
        wmma_chunk_mma4(sm.u.cv[buf], warp_r, acc);
        if (more) convert_chunk(sm.u.cv[buf ^ 1], tid, ar, wr);
        __syncthreads();
    }

#pragma unroll
    for (int i = 0; i < 2; i++)
#pragma unroll
        for (int j = 0; j < 4; j++)
            wmma::store_matrix_sync(&sm.u.C[warp_r * 32 + i * 16][j * 16],
                                    acc[i][j], 68, wmma::mem_row_major);
    __syncthreads();

    int tx = tid & 15, ty = tid >> 4;   // ty 0..7
    int c4 = tx * 4;
    float4 bv = *reinterpret_cast<const float4*>(&bias[c4]);
#pragma unroll
    for (int p = 0; p < 16; p++) {
        int r = ty + p * 8;
        int nid = __ldg(&ids[row0 + r]);
        float4 ev = *reinterpret_cast<const float4*>(&emb[(size_t)nid * CH + c4]);
        float4 o;
        o.x = sm.u.C[r][c4 + 0] + bv.x + ev.x;
        o.y = sm.u.C[r][c4 + 1] + bv.y + ev.y;
        o.z = sm.u.C[r][c4 + 2] + bv.z + ev.z;
        o.w = sm.u.C[r][c4 + 3] + bv.w + ev.w;
        *reinterpret_cast<float4*>(&out[(size_t)(row0 + r) * CH + c4]) = o;
    }
}

// ============================================================================
// Pipelined wmma thesis-SAGE GEMM (128 thr):
// out[128,64] = act( X[128,64]@W[64,64]^T + agg*inv + b )
// ============================================================================
template <bool RELU>
__global__ __launch_bounds__(128, 3)
void gemm64_wmma_kernel(const float* __restrict__ X, const float* __restrict__ W,
                        const float* __restrict__ bias,
                        const float* __restrict__ aggY, const float* __restrict__ inv,
                        float* __restrict__ out) {
    extern __shared__ char smraw[];
    PipeSmem& sm = *reinterpret_cast<PipeSmem*>(smraw);
    int tid = threadIdx.x;
    int warp_r = tid >> 5;
    int row0 = blockIdx.x * 128;

    wmma::fragment<wmma::accumulator, 16, 16, 16, float> acc[2][4];
#pragma unroll
    for (int i = 0; i < 2; i++)
#pragma unroll
        for (int j = 0; j < 4; j++) wmma::fill_fragment(acc[i][j], 0.0f);

    int a_r = tid >> 3;
    int cq  = (tid & 7) << 2;
    float4 ar[8], wr[4];

    // chunk 0 load + convert
#pragma unroll
    for (int j = 0; j < 8; j++)
        ar[j] = *reinterpret_cast<const float4*>(&X[(size_t)(row0 + a_r + 16 * j) * CH + cq]);
#pragma unroll
    for (int j = 0; j < 4; j++)
        wr[j] = *reinterpret_cast<const float4*>(&W[(size_t)(a_r + 16 * j) * CH + cq]);
    convert_chunk(sm.u.cv[0], tid, ar, wr);
    __syncthreads();

    // prefetch chunk 1
#pragma unroll
    for (int j = 0; j < 8; j++)
        ar[j] = *reinterpret_cast<const float4*>(&X[(size_t)(row0 + a_r + 16 * j) * CH + 32 + cq]);
#pragma unroll
    for (int j = 0; j < 4; j++)
        wr[j] = *reinterpret_cast<const float4*>(&W[(size_t)(a_r + 16 * j) * CH + 32 + cq]);

    wmma_chunk_mma4(sm.u.cv[0], warp_r, acc);
    convert_chunk(sm.u.cv[1], tid, ar, wr);
    __syncthreads();
    wmma_chunk_mma4(sm.u.cv[1], warp_r, acc);
    __syncthreads();

#pragma unroll
    for (int i = 0; i < 2; i++)
#pragma unroll
        for (int j = 0; j < 4; j++)
            wmma::store_matrix_sync(&sm.u.C[warp_r * 32 + i * 16][j * 16],
                                    acc[i][j], 68, wmma::mem_row_major);
    __syncthreads();

    int tx = tid & 15, ty = tid >> 4;
    int c4 = tx * 4;
    float4 bv = *reinterpret_cast<const float4*>(&bias[c4]);
#pragma unroll
    for (int p = 0; p < 16; p++) {
        int r = ty + p * 8;
        int gr = row0 + r;
        float sc = __ldg(&inv[gr]);
        float4 av = *reinterpret_cast<const float4*>(&aggY[(size_t)gr * CH + c4]);
        float4 o;
        o.x = fmaf(av.x, sc, sm.u.C[r][c4 + 0] + bv.x);
        o.y = fmaf(av.y, sc, sm.u.C[r][c4 + 1] + bv.y);
        o.z = fmaf(av.z, sc, sm.u.C[r][c4 + 2] + bv.z);
        o.w = fmaf(av.w, sc, sm.u.C[r][c4 + 3] + bv.w);
        if (RELU) {
            o.x = fmaxf(o.x, 0.f); o.y = fmaxf(o.y, 0.f);
            o.z = fmaxf(o.z, 0.f); o.w = fmaxf(o.w, 0.f);
        }
        *reinterpret_cast<float4*>(&out[(size_t)gr * CH + c4]) = o;
    }
}

// ---------------- K=64 FFMA2 GEMM (mentor-side, R4 proven body) ----------------
template <bool RELU, bool BIAS, bool ADDAGG>
__global__ __launch_bounds__(256)
void gemm64_kernel(const float* __restrict__ X, const float* __restrict__ W,
                   const float* __restrict__ bias,
                   const float* __restrict__ aggY, const float* __restrict__ inv,
                   float* __restrict__ out, int M) {
    __shared__ float As[32][132];
    __shared__ float Ws[32][68];
    int tid = threadIdx.x;
    int tx = tid & 15, ty = tid >> 4;
    int row0 = blockIdx.x * 128;

    float2 acc[4][4];
#pragma unroll
    for (int i = 0; i < 4; i++)
#pragma unroll
        for (int j = 0; j < 4; j++) acc[i][j] = make_float2(0.f, 0.f);

    for (int kt = 0; kt < CH; kt += 32) {
#pragma unroll
        for (int i = 0; i < 4; i++) {
            int idx = tid + 256 * i;
            int r = idx >> 3;
            int kq = (idx & 7) << 2;
            int grow = row0 + r;
            float4 v = make_float4(0.f, 0.f, 0.f, 0.f);
            if (grow < M)
                v = *reinterpret_cast<const float4*>(&X[(size_t)grow * CH + kt + kq]);
            As[kq + 0][r] = v.x; As[kq + 1][r] = v.y;
            As[kq + 2][r] = v.z; As[kq + 3][r] = v.w;
        }
#pragma unroll
        for (int i = 0; i < 2; i++) {
            int idx = tid + 256 * i;
            int c = idx >> 3;
            int kq = (idx & 7) << 2;
            float4 v = *reinterpret_cast<const float4*>(&W[(size_t)c * CH + kt + kq]);
            Ws[kq + 0][c] = v.x; Ws[kq + 1][c] = v.y;
            Ws[kq + 2][c] = v.z; Ws[kq + 3][c] = v.w;
        }
        __syncthreads();
#pragma unroll
        for (int k = 0; k < 32; k++) {
            float4 a0 = *reinterpret_cast<const float4*>(&As[k][ty * 8]);
            float4 a1 = *reinterpret_cast<const float4*>(&As[k][ty * 8 + 4]);
            float4 w  = *reinterpret_cast<const float4*>(&Ws[k][tx * 4]);
            float2 ap[4] = { {a0.x, a0.y}, {a0.z, a0.w}, {a1.x, a1.y}, {a1.z, a1.w} };
            float2 wd[4] = { {w.x, w.x}, {w.y, w.y}, {w.z, w.z}, {w.w, w.w} };
#pragma unroll
            for (int rp = 0; rp < 4; rp++)
#pragma unroll
                for (int j = 0; j < 4; j++)
                    acc[rp][j] = ffma2(ap[rp], wd[j], acc[rp][j]);
        }
        __syncthreads();
    }

    float4 bv = make_float4(0.f, 0.f, 0.f, 0.f);
    if (BIAS) bv = *reinterpret_cast<const float4*>(&bias[tx * 4]);
#pragma unroll
    for (int rp = 0; rp < 4; rp++) {
#pragma unroll
        for (int s = 0; s < 2; s++) {
            int r = row0 + ty * 8 + rp * 2 + s;
            if (r < M) {
                float4 o;
                o.x = (s ? acc[rp][0].y : acc[rp][0].x) + bv.x;
                o.y = (s ? acc[rp][1].y : acc[rp][1].x) + bv.y;
                o.z = (s ? acc[rp][2].y : acc[rp][2].x) + bv.z;
                o.w = (s ? acc[rp][3].y : acc[rp][3].x) + bv.w;
                if (ADDAGG) {
                    float sc = __ldg(&inv[r]);
                    float4 av = *reinterpret_cast<const float4*>(&aggY[(size_t)r * CH + tx * 4]);
                    o.x = fmaf(av.x, sc, o.x);
                    o.y = fmaf(av.y, sc, o.y);
                    o.z = fmaf(av.z, sc, o.z);
                    o.w = fmaf(av.w, sc, o.w);
                }
                if (RELU) {
                    o.x = fmaxf(o.x, 0.f); o.y = fmaxf(o.y, 0.f);
                    o.z = fmaxf(o.z, 0.f); o.w = fmaxf(o.w, 0.f);
                }
                *reinterpret_cast<float4*>(&out[(size_t)r * CH + tx * 4]) = o;
            }
        }
    }
}

// ---------------- mentor SAGE layer GEMM (K=128, R4 proven body) ---------------
template <bool RELU>
__global__ __launch_bounds__(256)
void sage_kernel(const float* __restrict__ Agg, const float* __restrict__ inv,
                 const float* __restrict__ Xs,
                 const float* __restrict__ Wl, const float* __restrict__ Wr,
                 const float* __restrict__ bias, float* __restrict__ out, int M) {
    __shared__ float As[32][132];
    __shared__ float Ws[32][68];
    int tid = threadIdx.x;
    int tx = tid & 15, ty = tid >> 4;
    int row0 = blockIdx.x * 128;

    float2 acc[4][4];
#pragma unroll
    for (int i = 0; i < 4; i++)
#pragma unroll
        for (int j = 0; j < 4; j++) acc[i][j] = make_float2(0.f, 0.f);

    for (int tt = 0; tt < 4; tt++) {
        const float* A  = (tt < 2) ? Agg : Xs;
        const float* Wp = (tt < 2) ? Wl  : Wr;
        bool do_scale = (tt < 2);
        int kt = (tt & 1) * 32;
#pragma unroll
        for (int i = 0; i < 4; i++) {
            int idx = tid + 256 * i;
            int r = idx >> 3;
            int kq = (idx & 7) << 2;
            int grow = row0 + r;
            float4 v = make_float4(0.f, 0.f, 0.f, 0.f);
            if (grow < M) {
                v = *reinterpret_cast<const float4*>(&A[(size_t)grow * CH + kt + kq]);
                if (do_scale) {
                    float sc = __ldg(&inv[grow]);
                    v.x *= sc; v.y *= sc; v.z *= sc; v.w *= sc;
                }
            }
            As[kq + 0][r] = v.x; As[kq + 1][r] = v.y;
            As[kq + 2][r] = v.z; As[kq + 3][r] = v.w;
        }
#pragma unroll
        for (int i = 0; i < 2; i++) {
            int idx = tid + 256 * i;
            int c = idx >> 3;
            int kq = (idx & 7) << 2;
            float4 v = *reinterpret_cast<const float4*>(&Wp[(size_t)c * CH + kt + kq]);
            Ws[kq + 0][c] = v.x; Ws[kq + 1][c] = v.y;
            Ws[kq + 2][c] = v.z; Ws[kq + 3][c] = v.w;
        }
        __syncthreads();
#pragma unroll
        for (int k = 0; k < 32; k++) {
            float4 a0 = *reinterpret_cast<const float4*>(&As[k][ty * 8]);
            float4 a1 = *reinterpret_cast<const float4*>(&As[k][ty * 8 + 4]);
            float4 w  = *reinterpret_cast<const float4*>(&Ws[k][tx * 4]);
            float2 ap[4] = { {a0.x, a0.y}, {a0.z, a0.w}, {a1.x, a1.y}, {a1.z, a1.w} };
            float2 wd[4] = { {w.x, w.x}, {w.y, w.y}, {w.z, w.z}, {w.w, w.w} };
#pragma unroll
            for (int rp = 0; rp < 4; rp++)
#pragma unroll
                for (int j = 0; j < 4; j++)
                    acc[rp][j] = ffma2(ap[rp], wd[j], acc[rp][j]);
        }
        __syncthreads();
    }

    float4 bv = *reinterpret_cast<const float4*>(&bias[tx * 4]);
#pragma unroll
    for (int rp = 0; rp < 4; rp++) {
#pragma unroll
        for (int s = 0; s < 2; s++) {
            int r = row0 + ty * 8 + rp * 2 + s;
            if (r < M) {
                float4 o;
                o.x = (s ? acc[rp][0].y : acc[rp][0].x) + bv.x;
                o.y = (s ? acc[rp][1].y : acc[rp][1].x) + bv.y;
                o.z = (s ? acc[rp][2].y : acc[rp][2].x) + bv.z;
                o.w = (s ? acc[rp][3].y : acc[rp][3].x) + bv.w;
                if (RELU) {
                    o.x = fmaxf(o.x, 0.f); o.y = fmaxf(o.y, 0.f);
                    o.z = fmaxf(o.z, 0.f); o.w = fmaxf(o.w, 0.f);
                }
                *reinterpret_cast<float4*>(&out[(size_t)r * CH + tx * 4]) = o;
            }
        }
    }
}

// ---------------- edge dot-product classifier --------------------------------
__global__ void edge_dot_kernel(const float* __restrict__ xt, const float* __restrict__ xm,
                                const int* __restrict__ es, const int* __restrict__ ed,
                                float* __restrict__ out, int E) {
    int t = blockIdx.x * blockDim.x + threadIdx.x;
    int e = t >> 4;
    if (e >= E) return;
    int c4 = (t & 15) << 2;
    int s = __ldg(&es[e]);
    int d = __ldg(&ed[e]);
    float4 a = *reinterpret_cast<const float4*>(&xt[(size_t)s * CH + c4]);
    float4 b = *reinterpret_cast<const float4*>(&xm[(size_t)d * CH + c4]);
    float p = a.x * b.x + a.y * b.y + a.z * b.z + a.w * b.w;
    p += __shfl_down_sync(0xffffffffu, p, 8);
    p += __shfl_down_sync(0xffffffffu, p, 4);
    p += __shfl_down_sync(0xffffffffu, p, 2);
    p += __shfl_down_sync(0xffffffffu, p, 1);
    if ((t & 15) == 0) out[e] = p;
}

// ---------------- launch -----------------------------------------------------
extern "C" void kernel_launch(void* const* d_in, const int* in_sizes, int n_in,
                              void* d_out, int out_size) {
    const float* x_thesis  = (const float*)d_in[0];
    const int*   thesis_id = (const int*)d_in[1];
    const int*   mentor_id = (const int*)d_in[2];
    const int*   edge_src  = (const int*)d_in[3];
    const int*   edge_dst  = (const int*)d_in[4];
    const int*   el_src    = (const int*)d_in[5];
    const int*   el_dst    = (const int*)d_in[6];
    const float* lin_W     = (const float*)d_in[7];
    const float* lin_b     = (const float*)d_in[8];
    const float* emb_t     = (const float*)d_in[9];
    const float* emb_m     = (const float*)d_in[10];
    const float* Wl_tm0    = (const float*)d_in[11];
    const float* Wr_tm0    = (const float*)d_in[12];
    const float* b_tm0     = (const float*)d_in[13];
    const float* Wl_mt0    = (const float*)d_in[14];
    const float* Wr_mt0    = (const float*)d_in[15];
    const float* b_mt0     = (const float*)d_in[16];
    const float* Wl_tm1    = (const float*)d_in[17];
    const float* Wr_tm1    = (const float*)d_in[18];
    const float* b_tm1     = (const float*)d_in[19];
    const float* Wl_mt1    = (const float*)d_in[20];
    const float* Wr_mt1    = (const float*)d_in[21];
    const float* b_mt1     = (const float*)d_in[22];
    float* out = (float*)d_out;

    int nt = in_sizes[1];
    int nm = in_sizes[2];
    int E  = in_sizes[3];
    int EL = in_sizes[5];

    void *p_xt0, *p_xt1, *p_xt2, *p_aggt, *p_xm0, *p_xm1, *p_xm2, *p_aggm, *p_ym;
    void *p_cntt, *p_cntm, *p_invt, *p_invm;
    cudaGetSymbolAddress(&p_xt0, g_xt0);   cudaGetSymbolAddress(&p_xt1, g_xt1);
    cudaGetSymbolAddress(&p_xt2, g_xt2);   cudaGetSymbolAddress(&p_aggt, g_aggt);
    cudaGetSymbolAddress(&p_xm0, g_xm0);   cudaGetSymbolAddress(&p_xm1, g_xm1);
    cudaGetSymbolAddress(&p_xm2, g_xm2);   cudaGetSymbolAddress(&p_aggm, g_aggm);
    cudaGetSymbolAddress(&p_ym, g_ym);
    cudaGetSymbolAddress(&p_cntt, g_cnt_t); cudaGetSymbolAddress(&p_cntm, g_cnt_m);
    cudaGetSymbolAddress(&p_invt, g_inv_t); cudaGetSymbolAddress(&p_invm, g_inv_m);

    float* xt0 = (float*)p_xt0; float* xt1 = (float*)p_xt1; float* xt2 = (float*)p_xt2;
    float* aggt = (float*)p_aggt;
    float* xm0 = (float*)p_xm0; float* xm1 = (float*)p_xm1; float* xm2 = (float*)p_xm2;
    float* aggm = (float*)p_aggm; float* ym = (float*)p_ym;
    int* cntt = (int*)p_cntt; int* cntm = (int*)p_cntm;
    float* invt = (float*)p_invt; float* invm = (float*)p_invm;

    cudaFuncSetAttribute(encoder_wmma_kernel,
                         cudaFuncAttributeMaxDynamicSharedMemorySize, PIPE_SMEM);
    cudaFuncSetAttribute(gemm64_wmma_kernel<true>,
                         cudaFuncAttributeMaxDynamicSharedMemorySize, PIPE_SMEM);
    cudaFuncSetAttribute(gemm64_wmma_kernel<false>,
                         cudaFuncAttributeMaxDynamicSharedMemorySize, PIPE_SMEM);

    const int TB = 256;
    int gridE16  = (E * 16 + TB - 1) / TB;
    int gridEL16 = (EL * 16 + TB - 1) / TB;
    int gridNT   = (nt + 127) / 128;
    int gridNM   = (nm + 127) / 128;

    // ---- exactly 5 launches before the encoder so ncu (-s 5 -c 1) captures it --
    cudaMemsetAsync(cntt, 0, (size_t)nt * sizeof(int));
    cudaMemsetAsync(cntm, 0, (size_t)nm * sizeof(int));
    degree_kernel<<<(E + TB - 1) / TB, TB>>>(edge_src, edge_dst, E);
    recip_kernel<<<(nt + TB - 1) / TB, TB>>>(cntt, invt, nt);
    recip_kernel<<<(nm + TB - 1) / TB, TB>>>(cntm, invm, nm);

    encoder_wmma_kernel<<<gridNT, 128, PIPE_SMEM>>>(x_thesis, lin_W, lin_b, emb_t,
                                                    thesis_id, xt0);
    gather_rows_kernel<<<(nm * 16 + TB - 1) / TB, TB>>>(emb_m, mentor_id, xm0, nm);

    // ---- layer 0 ----
    gemm64_kernel<false, false, false><<<gridNM, TB>>>(xm0, Wl_mt0, nullptr, nullptr, nullptr, ym, nm);
    cudaMemsetAsync(aggm, 0, (size_t)nm * CH * sizeof(float));
    cudaMemsetAsync(aggt, 0, (size_t)nt * CH * sizeof(float));
    scatter_kernel<<<gridE16, TB>>>(xt0, edge_src, edge_dst, aggm, E);
    scatter_kernel<<<gridE16, TB>>>(ym, edge_dst, edge_src, aggt, E);
    sage_kernel<true><<<gridNM, TB>>>(aggm, invm, xm0, Wl_tm0, Wr_tm0, b_tm0, xm1, nm);
    gemm64_wmma_kernel<true><<<gridNT, 128, PIPE_SMEM>>>(xt0, Wr_mt0, b_mt0, aggt, invt, xt1);

    // ---- layer 1 ----
    gemm64_kernel<false, false, false><<<gridNM, TB>>>(xm1, Wl_mt1, nullptr, nullptr, nullptr, ym, nm);
    cudaMemsetAsync(aggm, 0, (size_t)nm * CH * sizeof(float));
    cudaMemsetAsync(aggt, 0, (size_t)nt * CH * sizeof(float));
    scatter_kernel<<<gridE16, TB>>>(xt1, edge_src, edge_dst, aggm, E);
    scatter_kernel<<<gridE16, TB>>>(ym, edge_dst, edge_src, aggt, E);
    sage_kernel<false><<<gridNM, TB>>>(aggm, invm, xm1, Wl_tm1, Wr_tm1, b_tm1, xm2, nm);
    gemm64_wmma_kernel<false><<<gridNT, 128, PIPE_SMEM>>>(xt1, Wr_mt1, b_mt1, aggt, invt, xt2);

    // classifier
    edge_dot_kernel<<<gridEL16, TB>>>(xt2, xm2, el_src, el_dst, out, EL);
}

// round 14
// speedup vs baseline: 1.1770x; 1.0753x over previous
#include <cuda_runtime.h>
#include <cuda_bf16.h>
#include <mma.h>
#include <cstdint>
#include <cstddef>

using namespace nvcuda;

// Problem dims (fixed by dataset)
#define NTC 400000
#define NMC 40000
#define CH  64
#define FT  384

// ---------------- scratch (static __device__ — no allocations) ----------------
__device__ float g_xt0[(size_t)NTC * CH];
__device__ float g_xt1[(size_t)NTC * CH];
__device__ float g_xt2[(size_t)NTC * CH];
__device__ float g_xm0[(size_t)NMC * CH];
__device__ float g_xm1[(size_t)NMC * CH];
__device__ float g_xm2[(size_t)NMC * CH];
__device__ float g_aggm[(size_t)NMC * CH];
__device__ float g_ym[(size_t)NMC * CH];
__device__ int   g_cnt_t[NTC];
__device__ int   g_cnt_m[NMC];
__device__ float g_inv_t[NTC];
__device__ float g_inv_m[NMC];

// ---------------- packed f32x2 FMA ----------------
union F2U { float2 f; unsigned long long u; };
__device__ __forceinline__ float2 ffma2(float2 a, float2 b, float2 c) {
    F2U A, B, Cc, D;
    A.f = a; B.f = b; Cc.f = c;
    asm("fma.rn.f32x2 %0, %1, %2, %3;" : "=l"(D.u) : "l"(A.u), "l"(B.u), "l"(Cc.u));
    return D.f;
}

// ---------------- degree / recip ----------------
__global__ void degree_kernel(const int* __restrict__ esrc, const int* __restrict__ edst, int E) {
    int t = blockIdx.x * blockDim.x + threadIdx.x;
    if (t < E) {
        atomicAdd(&g_cnt_t[esrc[t]], 1);
        atomicAdd(&g_cnt_m[edst[t]], 1);
    }
}

__global__ void recip_kernel(const int* __restrict__ cnt, float* __restrict__ inv, int n) {
    int t = blockIdx.x * blockDim.x + threadIdx.x;
    if (t < n) inv[t] = 1.0f / fmaxf((float)cnt[t], 1.0f);
}

// ---------------- mentor encoder: x_m0 = emb_m[mentor_id] ----------------
__global__ void gather_rows_kernel(const float* __restrict__ src, const int* __restrict__ ids,
                                   float* __restrict__ out, int n) {
    int t = blockIdx.x * blockDim.x + threadIdx.x;
    int e = t >> 4;
    if (e >= n) return;
    int c4 = (t & 15) << 2;
    int id = __ldg(&ids[e]);
    float4 v = *reinterpret_cast<const float4*>(&src[(size_t)id * CH + c4]);
    *reinterpret_cast<float4*>(&out[(size_t)e * CH + c4]) = v;
}

// ---------------- edge scatter-add: agg[sidx[e]] += relu?(feat[gidx[e]]) -------
template <bool RELU_IN>
__global__ void scatter_kernel(const float* __restrict__ feat, const int* __restrict__ gidx,
                               const int* __restrict__ sidx, float* __restrict__ agg, int E) {
    int t = blockIdx.x * blockDim.x + threadIdx.x;
    int e = t >> 4;
    if (e >= E) return;
    int c4 = (t & 15) << 2;
    int s = __ldg(&gidx[e]);
    int d = __ldg(&sidx[e]);
    float4 v = *reinterpret_cast<const float4*>(&feat[(size_t)s * CH + c4]);
    if (RELU_IN) {
        v.x = fmaxf(v.x, 0.f); v.y = fmaxf(v.y, 0.f);
        v.z = fmaxf(v.z, 0.f); v.w = fmaxf(v.w, 0.f);
    }
    float* p = &agg[(size_t)d * CH + c4];
    asm volatile("red.global.add.v4.f32 [%0], {%1, %2, %3, %4};"
                 :: "l"(p), "f"(v.x), "f"(v.y), "f"(v.z), "f"(v.w) : "memory");
}

// ---------------- scaled edge scatter: out[src[e]] += ym[dst[e]] * inv[src[e]] --
__global__ void scatter_scaled_kernel(const float* __restrict__ ym,
                                      const int* __restrict__ edst,
                                      const int* __restrict__ esrc,
                                      const float* __restrict__ inv,
                                      float* __restrict__ out, int E) {
    int t = blockIdx.x * blockDim.x + threadIdx.x;
    int e = t >> 4;
    if (e >= E) return;
    int c4 = (t & 15) << 2;
    int d = __ldg(&edst[e]);
    int s = __ldg(&esrc[e]);
    float sc = __ldg(&inv[s]);
    float4 v = *reinterpret_cast<const float4*>(&ym[(size_t)d * CH + c4]);
    v.x *= sc; v.y *= sc; v.z *= sc; v.w *= sc;
    float* p = &out[(size_t)s * CH + c4];
    asm volatile("red.global.add.v4.f32 [%0], {%1, %2, %3, %4};"
                 :: "l"(p), "f"(v.x), "f"(v.y), "f"(v.z), "f"(v.w) : "memory");
}

// ============================================================================
// wmma bf16-split machinery — 4 warps, warp tile 32x64, double-buffered cv
// ============================================================================
#define AST 40   // smem k-stride (elements), mult of 8 for wmma ldm

struct CvBufs {
    __nv_bfloat16 Ahi[128][AST];
    __nv_bfloat16 Alo[128][AST];
    __nv_bfloat16 Bhi[64][AST];
    __nv_bfloat16 Blo[64][AST];
};

struct PipeSmem {
    union {
        CvBufs cv[2];
        float C[128][68];
    } u;
};
#define PIPE_SMEM ((int)sizeof(PipeSmem))

__device__ __forceinline__ void cvt_store_split(__nv_bfloat16* hi_p, __nv_bfloat16* lo_p,
                                                float4 v) {
    __nv_bfloat162 h01 = __floats2bfloat162_rn(v.x, v.y);
    __nv_bfloat162 h23 = __floats2bfloat162_rn(v.z, v.w);
    float2 f01 = __bfloat1622float2(h01);
    float2 f23 = __bfloat1622float2(h23);
    __nv_bfloat162 l01 = __floats2bfloat162_rn(v.x - f01.x, v.y - f01.y);
    __nv_bfloat162 l23 = __floats2bfloat162_rn(v.z - f23.x, v.w - f23.y);
    *reinterpret_cast<uint2*>(hi_p) = make_uint2(
        *reinterpret_cast<uint32_t*>(&h01), *reinterpret_cast<uint32_t*>(&h23));
    *reinterpret_cast<uint2*>(lo_p) = make_uint2(
        *reinterpret_cast<uint32_t*>(&l01), *reinterpret_cast<uint32_t*>(&l23));
}

// convert staged regs into cv buffer (A: 8 f4/thread, B: 4 f4/thread, 128 thr)
__device__ __forceinline__ void convert_chunk(CvBufs& cv, int tid,
                                              const float4 (&ar)[8], const float4 (&wr)[4]) {
#pragma unroll
    for (int j = 0; j < 8; j++) {
        int idx = tid + 128 * j;
        int r = idx >> 3, cq = (idx & 7) << 2;
        cvt_store_split(&cv.Ahi[r][cq], &cv.Alo[r][cq], ar[j]);
    }
#pragma unroll
    for (int j = 0; j < 4; j++) {
        int idx = tid + 128 * j;
        int r = idx >> 3, cq = (idx & 7) << 2;
        cvt_store_split(&cv.Bhi[r][cq], &cv.Blo[r][cq], wr[j]);
    }
}

// warp computes 32x64 tile: 2x4 accumulators, 3 split terms per 16-k step
__device__ __forceinline__ void wmma_chunk_mma4(
    CvBufs& cv, int warp_r,
    wmma::fragment<wmma::accumulator, 16, 16, 16, float> (&acc)[2][4]) {
#pragma unroll
    for (int kk = 0; kk < 32; kk += 16) {
        wmma::fragment<wmma::matrix_a, 16, 16, 16, __nv_bfloat16, wmma::row_major> ah[2], al[2];
#pragma unroll
        for (int i = 0; i < 2; i++) {
            wmma::load_matrix_sync(ah[i], &cv.Ahi[warp_r * 32 + i * 16][kk], AST);
            wmma::load_matrix_sync(al[i], &cv.Alo[warp_r * 32 + i * 16][kk], AST);
        }
#pragma unroll
        for (int j = 0; j < 4; j++) {
            wmma::fragment<wmma::matrix_b, 16, 16, 16, __nv_bfloat16, wmma::col_major> bh, bl;
            wmma::load_matrix_sync(bh, &cv.Bhi[j * 16][kk], AST);
            wmma::load_matrix_sync(bl, &cv.Blo[j * 16][kk], AST);
#pragma unroll
            for (int i = 0; i < 2; i++) {
                wmma::mma_sync(acc[i][j], ah[i], bh, acc[i][j]);
                wmma::mma_sync(acc[i][j], ah[i], bl, acc[i][j]);
                wmma::mma_sync(acc[i][j], al[i], bh, acc[i][j]);
            }
        }
    }
}

__device__ __forceinline__ float4 relu4(float4 v) {
    v.x = fmaxf(v.x, 0.f); v.y = fmaxf(v.y, 0.f);
    v.z = fmaxf(v.z, 0.f); v.w = fmaxf(v.w, 0.f);
    return v;
}

// ============================================================================
// Pipelined wmma encoder (128 thr): out[128,64] = X[128,384]@W[64,384]^T+b+emb
// ============================================================================
__global__ __launch_bounds__(128, 3)
void encoder_wmma_kernel(const float* __restrict__ X, const float* __restrict__ W,
                         const float* __restrict__ bias, const float* __restrict__ emb,
                         const int* __restrict__ ids, float* __restrict__ out) {
    extern __shared__ char smraw[];
    PipeSmem& sm = *reinterpret_cast<PipeSmem*>(smraw);
    int tid = threadIdx.x;
    int warp_r = tid >> 5;
    int row0 = blockIdx.x * 128;

    wmma::fragment<wmma::accumulator, 16, 16, 16, float> acc[2][4];
#pragma unroll
    for (int i = 0; i < 2; i++)
#pragma unroll
        for (int j = 0; j < 4; j++) wmma::fill_fragment(acc[i][j], 0.0f);

    int a_r = tid >> 3;
    int cq  = (tid & 7) << 2;
    float4 ar[8], wr[4];

#pragma unroll
    for (int j = 0; j < 8; j++)
        ar[j] = *reinterpret_cast<const float4*>(&X[(size_t)(row0 + a_r + 16 * j) * FT + cq]);
#pragma unroll
    for (int j = 0; j < 4; j++)
        wr[j] = *reinterpret_cast<const float4*>(&W[(size_t)(a_r + 16 * j) * FT + cq]);
    convert_chunk(sm.u.cv[0], tid, ar, wr);
    __syncthreads();

    const int NC = FT / 32;  // 12
    for (int ch = 0; ch < NC; ch++) {
        int buf = ch & 1;
        bool more = (ch + 1 < NC);
        if (more) {
            int kt = (ch + 1) * 32;
#pragma unroll
            for (int j = 0; j < 8; j++)
                ar[j] = *reinterpret_cast<const float4*>(
                    &X[(size_t)(row0 + a_r + 16 * j) * FT + kt + cq]);
#pragma unroll
            for (int j = 0; j < 4; j++)
                wr[j] = *reinterpret_cast<const float4*>(
                    &W[(size_t)(a_r + 16 * j) * FT + kt + cq]);
        }
        wmma_chunk_mma4(sm.u.cv[buf], warp_r, acc);
        if (more) convert_chunk(sm.u.cv[buf ^ 1], tid, ar, wr);
        __syncthreads();
    }

#pragma unroll
    for (int i = 0; i < 2; i++)
#pragma unroll
        for (int j = 0; j < 4; j++)
            wmma::store_matrix_sync(&sm.u.C[warp_r * 32 + i * 16][j * 16],
                                    acc[i][j], 68, wmma::mem_row_major);
    __syncthreads();

    int tx = tid & 15, ty = tid >> 4;
    int c4 = tx * 4;
    float4 bv = *reinterpret_cast<const float4*>(&bias[c4]);
#pragma unroll
    for (int p = 0; p < 16; p++) {
        int r = ty + p * 8;
        int nid = __ldg(&ids[row0 + r]);
        float4 ev = *reinterpret_cast<const float4*>(&emb[(size_t)nid * CH + c4]);
        float4 o;
        o.x = sm.u.C[r][c4 + 0] + bv.x + ev.x;
        o.y = sm.u.C[r][c4 + 1] + bv.y + ev.y;
        o.z = sm.u.C[r][c4 + 2] + bv.z + ev.z;
        o.w = sm.u.C[r][c4 + 3] + bv.w + ev.w;
        *reinterpret_cast<float4*>(&out[(size_t)(row0 + r) * CH + c4]) = o;
    }
}

// ============================================================================
// Pipelined wmma thesis base GEMM (128 thr):
// out[128,64] = relu_in?(X)[128,64]@W[64,64]^T + b      (agg added later by
// scatter_scaled; NO output relu — readers apply it)
// ============================================================================
template <bool RELU_IN>
__global__ __launch_bounds__(128, 3)
void gemm64_wmma_kernel(const float* __restrict__ X, const float* __restrict__ W,
                        const float* __restrict__ bias, float* __restrict__ out) {
    extern __shared__ char smraw[];
    PipeSmem& sm = *reinterpret_cast<PipeSmem*>(smraw);
    int tid = threadIdx.x;
    int warp_r = tid >> 5;
    int row0 = blockIdx.x * 128;

    wmma::fragment<wmma::accumulator, 16, 16, 16, float> acc[2][4];
#pragma unroll
    for (int i = 0; i < 2; i++)
#pragma unroll
        for (int j = 0; j < 4; j++) wmma::fill_fragment(acc[i][j], 0.0f);

    int a_r = tid >> 3;
    int cq  = (tid & 7) << 2;
    float4 ar[8], wr[4];

#pragma unroll
    for (int j = 0; j < 8; j++) {
        ar[j] = *reinterpret_cast<const float4*>(&X[(size_t)(row0 + a_r + 16 * j) * CH + cq]);
        if (RELU_IN) ar[j] = relu4(ar[j]);
    }
#pragma unroll
    for (int j = 0; j < 4; j++)
        wr[j] = *reinterpret_cast<const float4*>(&W[(size_t)(a_r + 16 * j) * CH + cq]);
    convert_chunk(sm.u.cv[0], tid, ar, wr);
    __syncthreads();

#pragma unroll
    for (int j = 0; j < 8; j++) {
        ar[j] = *reinterpret_cast<const float4*>(&X[(size_t)(row0 + a_r + 16 * j) * CH + 32 + cq]);
        if (RELU_IN) ar[j] = relu4(ar[j]);
    }
#pragma unroll
    for (int j = 0; j < 4; j++)
        wr[j] = *reinterpret_cast<const float4*>(&W[(size_t)(a_r + 16 * j) * CH + 32 + cq]);

    wmma_chunk_mma4(sm.u.cv[0], warp_r, acc);
    convert_chunk(sm.u.cv[1], tid, ar, wr);
    __syncthreads();
    wmma_chunk_mma4(sm.u.cv[1], warp_r, acc);
    __syncthreads();

#pragma unroll
    for (int i = 0; i < 2; i++)
#pragma unroll
        for (int j = 0; j < 4; j++)
            wmma::store_matrix_sync(&sm.u.C[warp_r * 32 + i * 16][j * 16],
                                    acc[i][j], 68, wmma::mem_row_major);
    __syncthreads();

    int tx = tid & 15, ty = tid >> 4;
    int c4 = tx * 4;
    float4 bv = *reinterpret_cast<const float4*>(&bias[c4]);
#pragma unroll
    for (int p = 0; p < 16; p++) {
        int r = ty + p * 8;
        int gr = row0 + r;
        float4 o;
        o.x = sm.u.C[r][c4 + 0] + bv.x;
        o.y = sm.u.C[r][c4 + 1] + bv.y;
        o.z = sm.u.C[r][c4 + 2] + bv.z;
        o.w = sm.u.C[r][c4 + 3] + bv.w;
        *reinterpret_cast<float4*>(&out[(size_t)gr * CH + c4]) = o;
    }
}

// ---------------- K=64 FFMA2 GEMM (mentor ym, R4 proven body) ------------------
template <bool RELU, bool BIAS>
__global__ __launch_bounds__(256)
void gemm64_kernel(const float* __restrict__ X, const float* __restrict__ W,
                   const float* __restrict__ bias, float* __restrict__ out, int M) {
    __shared__ float As[32][132];
    __shared__ float Ws[32][68];
    int tid = threadIdx.x;
    int tx = tid & 15, ty = tid >> 4;
    int row0 = blockIdx.x * 128;

    float2 acc[4][4];
#pragma unroll
    for (int i = 0; i < 4; i++)
#pragma unroll
        for (int j = 0; j < 4; j++) acc[i][j] = make_float2(0.f, 0.f);

    for (int kt = 0; kt < CH; kt += 32) {
#pragma unroll
        for (int i = 0; i < 4; i++) {
            int idx = tid + 256 * i;
            int r = idx >> 3;
            int kq = (idx & 7) << 2;
            int grow = row0 + r;
            float4 v = make_float4(0.f, 0.f, 0.f, 0.f);
            if (grow < M)
                v = *reinterpret_cast<const float4*>(&X[(size_t)grow * CH + kt + kq]);
            As[kq + 0][r] = v.x; As[kq + 1][r] = v.y;
            As[kq + 2][r] = v.z; As[kq + 3][r] = v.w;
        }
#pragma unroll
        for (int i = 0; i < 2; i++) {
            int idx = tid + 256 * i;
            int c = idx >> 3;
            int kq = (idx & 7) << 2;
            float4 v = *reinterpret_cast<const float4*>(&W[(size_t)c * CH + kt + kq]);
            Ws[kq + 0][c] = v.x; Ws[kq + 1][c] = v.y;
            Ws[kq + 2][c] = v.z; Ws[kq + 3][c] = v.w;
        }
        __syncthreads();
#pragma unroll
        for (int k = 0; k < 32; k++) {
            float4 a0 = *reinterpret_cast<const float4*>(&As[k][ty * 8]);
            float4 a1 = *reinterpret_cast<const float4*>(&As[k][ty * 8 + 4]);
            float4 w  = *reinterpret_cast<const float4*>(&Ws[k][tx * 4]);
            float2 ap[4] = { {a0.x, a0.y}, {a0.z, a0.w}, {a1.x, a1.y}, {a1.z, a1.w} };
            float2 wd[4] = { {w.x, w.x}, {w.y, w.y}, {w.z, w.z}, {w.w, w.w} };
#pragma unroll
            for (int rp = 0; rp < 4; rp++)
#pragma unroll
                for (int j = 0; j < 4; j++)
                    acc[rp][j] = ffma2(ap[rp], wd[j], acc[rp][j]);
        }
        __syncthreads();
    }

    float4 bv = make_float4(0.f, 0.f, 0.f, 0.f);
    if (BIAS) bv = *reinterpret_cast<const float4*>(&bias[tx * 4]);
#pragma unroll
    for (int rp = 0; rp < 4; rp++) {
#pragma unroll
        for (int s = 0; s < 2; s++) {
            int r = row0 + ty * 8 + rp * 2 + s;
            if (r < M) {
                float4 o;
                o.x = (s ? acc[rp][0].y : acc[rp][0].x) + bv.x;
                o.y = (s ? acc[rp][1].y : acc[rp][1].x) + bv.y;
                o.z = (s ? acc[rp][2].y : acc[rp][2].x) + bv.z;
                o.w = (s ? acc[rp][3].y : acc[rp][3].x) + bv.w;
                if (RELU) {
                    o.x = fmaxf(o.x, 0.f); o.y = fmaxf(o.y, 0.f);
                    o.z = fmaxf(o.z, 0.f); o.w = fmaxf(o.w, 0.f);
                }
                *reinterpret_cast<float4*>(&out[(size_t)r * CH + tx * 4]) = o;
            }
        }
    }
}

// ---------------- mentor SAGE layer GEMM (K=128, R4 proven body) ---------------
template <bool RELU>
__global__ __launch_bounds__(256)
void sage_kernel(const float* __restrict__ Agg, const float* __restrict__ inv,
                 const float* __restrict__ Xs,
                 const float* __restrict__ Wl, const float* __restrict__ Wr,
                 const float* __restrict__ bias, float* __restrict__ out, int M) {
    __shared__ float As[32][132];
    __shared__ float Ws[32][68];
    int tid = threadIdx.x;
    int tx = tid & 15, ty = tid >> 4;
    int row0 = blockIdx.x * 128;

    float2 acc[4][4];
#pragma unroll
    for (int i = 0; i < 4; i++)
#pragma unroll
        for (int j = 0; j < 4; j++) acc[i][j] = make_float2(0.f, 0.f);

    for (int tt = 0; tt < 4; tt++) {
        const float* A  = (tt < 2) ? Agg : Xs;
        const float* Wp = (tt < 2) ? Wl  : Wr;
        bool do_scale = (tt < 2);
        int kt = (tt & 1) * 32;
#pragma unroll
        for (int i = 0; i < 4; i++) {
            int idx = tid + 256 * i;
            int r = idx >> 3;
            int kq = (idx & 7) << 2;
            int grow = row0 + r;
            float4 v = make_float4(0.f, 0.f, 0.f, 0.f);
            if (grow < M) {
                v = *reinterpret_cast<const float4*>(&A[(size_t)grow * CH + kt + kq]);
                if (do_scale) {
                    float sc = __ldg(&inv[grow]);
                    v.x *= sc; v.y *= sc; v.z *= sc; v.w *= sc;
                }
            }
            As[kq + 0][r] = v.x; As[kq + 1][r] = v.y;
            As[kq + 2][r] = v.z; As[kq + 3][r] = v.w;
        }
#pragma unroll
        for (int i = 0; i < 2; i++) {
            int idx = tid + 256 * i;
            int c = idx >> 3;
            int kq = (idx & 7) << 2;
            float4 v = *reinterpret_cast<const float4*>(&Wp[(size_t)c * CH + kt + kq]);
            Ws[kq + 0][c] = v.x; Ws[kq + 1][c] = v.y;
            Ws[kq + 2][c] = v.z; Ws[kq + 3][c] = v.w;
        }
        __syncthreads();
#pragma unroll
        for (int k = 0; k < 32; k++) {
            float4 a0 = *reinterpret_cast<const float4*>(&As[k][ty * 8]);
            float4 a1 = *reinterpret_cast<const float4*>(&As[k][ty * 8 + 4]);
            float4 w  = *reinterpret_cast<const float4*>(&Ws[k][tx * 4]);
            float2 ap[4] = { {a0.x, a0.y}, {a0.z, a0.w}, {a1.x, a1.y}, {a1.z, a1.w} };
            float2 wd[4] = { {w.x, w.x}, {w.y, w.y}, {w.z, w.z}, {w.w, w.w} };
#pragma unroll
            for (int rp = 0; rp < 4; rp++)
#pragma unroll
                for (int j = 0; j < 4; j++)
                    acc[rp][j] = ffma2(ap[rp], wd[j], acc[rp][j]);
        }
        __syncthreads();
    }

    float4 bv = *reinterpret_cast<const float4*>(&bias[tx * 4]);
#pragma unroll
    for (int rp = 0; rp < 4; rp++) {
#pragma unroll
        for (int s = 0; s < 2; s++) {
            int r = row0 + ty * 8 + rp * 2 + s;
            if (r < M) {
                float4 o;
                o.x = (s ? acc[rp][0].y : acc[rp][0].x) + bv.x;
                o.y = (s ? acc[rp][1].y : acc[rp][1].x) + bv.y;
                o.z = (s ? acc[rp][2].y : acc[rp][2].x) + bv.z;
                o.w = (s ? acc[rp][3].y : acc[rp][3].x) + bv.w;
                if (RELU) {
                    o.x = fmaxf(o.x, 0.f); o.y = fmaxf(o.y, 0.f);
                    o.z = fmaxf(o.z, 0.f); o.w = fmaxf(o.w, 0.f);
                }
                *reinterpret_cast<float4*>(&out[(size_t)r * CH + tx * 4]) = o;
            }
        }
    }
}

// ---------------- edge dot-product classifier --------------------------------
__global__ void edge_dot_kernel(const float* __restrict__ xt, const float* __restrict__ xm,
                                const int* __restrict__ es, const int* __restrict__ ed,
                                float* __restrict__ out, int E) {
    int t = blockIdx.x * blockDim.x + threadIdx.x;
    int e = t >> 4;
    if (e >= E) return;
    int c4 = (t & 15) << 2;
    int s = __ldg(&es[e]);
    int d = __ldg(&ed[e]);
    float4 a = *reinterpret_cast<const float4*>(&xt[(size_t)s * CH + c4]);
    float4 b = *reinterpret_cast<const float4*>(&xm[(size_t)d * CH + c4]);
    float p = a.x * b.x + a.y * b.y + a.z * b.z + a.w * b.w;
    p += __shfl_down_sync(0xffffffffu, p, 8);
    p += __shfl_down_sync(0xffffffffu, p, 4);
    p += __shfl_down_sync(0xffffffffu, p, 2);
    p += __shfl_down_sync(0xffffffffu, p, 1);
    if ((t & 15) == 0) out[e] = p;
}

// ---------------- launch -----------------------------------------------------
extern "C" void kernel_launch(void* const* d_in, const int* in_sizes, int n_in,
                              void* d_out, int out_size) {
    const float* x_thesis  = (const float*)d_in[0];
    const int*   thesis_id = (const int*)d_in[1];
    const int*   mentor_id = (const int*)d_in[2];
    const int*   edge_src  = (const int*)d_in[3];
    const int*   edge_dst  = (const int*)d_in[4];
    const int*   el_src    = (const int*)d_in[5];
    const int*   el_dst    = (const int*)d_in[6];
    const float* lin_W     = (const float*)d_in[7];
    const float* lin_b     = (const float*)d_in[8];
    const float* emb_t     = (const float*)d_in[9];
    const float* emb_m     = (const float*)d_in[10];
    const float* Wl_tm0    = (const float*)d_in[11];
    const float* Wr_tm0    = (const float*)d_in[12];
    const float* b_tm0     = (const float*)d_in[13];
    const float* Wl_mt0    = (const float*)d_in[14];
    const float* Wr_mt0    = (const float*)d_in[15];
    const float* b_mt0     = (const float*)d_in[16];
    const float* Wl_tm1    = (const float*)d_in[17];
    const float* Wr_tm1    = (const float*)d_in[18];
    const float* b_tm1     = (const float*)d_in[19];
    const float* Wl_mt1    = (const float*)d_in[20];
    const float* Wr_mt1    = (const float*)d_in[21];
    const float* b_mt1     = (const float*)d_in[22];
    float* out = (float*)d_out;

    int nt = in_sizes[1];
    int nm = in_sizes[2];
    int E  = in_sizes[3];
    int EL = in_sizes[5];

    void *p_xt0, *p_xt1, *p_xt2, *p_xm0, *p_xm1, *p_xm2, *p_aggm, *p_ym;
    void *p_cntt, *p_cntm, *p_invt, *p_invm;
    cudaGetSymbolAddress(&p_xt0, g_xt0);   cudaGetSymbolAddress(&p_xt1, g_xt1);
    cudaGetSymbolAddress(&p_xt2, g_xt2);
    cudaGetSymbolAddress(&p_xm0, g_xm0);   cudaGetSymbolAddress(&p_xm1, g_xm1);
    cudaGetSymbolAddress(&p_xm2, g_xm2);   cudaGetSymbolAddress(&p_aggm, g_aggm);
    cudaGetSymbolAddress(&p_ym, g_ym);
    cudaGetSymbolAddress(&p_cntt, g_cnt_t); cudaGetSymbolAddress(&p_cntm, g_cnt_m);
    cudaGetSymbolAddress(&p_invt, g_inv_t); cudaGetSymbolAddress(&p_invm, g_inv_m);

    float* xt0 = (float*)p_xt0; float* xt1 = (float*)p_xt1; float* xt2 = (float*)p_xt2;
    float* xm0 = (float*)p_xm0; float* xm1 = (float*)p_xm1; float* xm2 = (float*)p_xm2;
    float* aggm = (float*)p_aggm; float* ym = (float*)p_ym;
    int* cntt = (int*)p_cntt; int* cntm = (int*)p_cntm;
    float* invt = (float*)p_invt; float* invm = (float*)p_invm;

    cudaFuncSetAttribute(encoder_wmma_kernel,
                         cudaFuncAttributeMaxDynamicSharedMemorySize, PIPE_SMEM);
    cudaFuncSetAttribute(gemm64_wmma_kernel<true>,
                         cudaFuncAttributeMaxDynamicSharedMemorySize, PIPE_SMEM);
    cudaFuncSetAttribute(gemm64_wmma_kernel<false>,
                         cudaFuncAttributeMaxDynamicSharedMemorySize, PIPE_SMEM);

    const int TB = 256;
    int gridE16  = (E * 16 + TB - 1) / TB;
    int gridEL16 = (EL * 16 + TB - 1) / TB;
    int gridNT   = (nt + 127) / 128;
    int gridNM   = (nm + 127) / 128;

    // ---- exactly 5 launches before the encoder so ncu (-s 5 -c 1) captures it --
    cudaMemsetAsync(cntt, 0, (size_t)nt * sizeof(int));
    cudaMemsetAsync(cntm, 0, (size_t)nm * sizeof(int));
    degree_kernel<<<(E + TB - 1) / TB, TB>>>(edge_src, edge_dst, E);
    recip_kernel<<<(nt + TB - 1) / TB, TB>>>(cntt, invt, nt);
    recip_kernel<<<(nm + TB - 1) / TB, TB>>>(cntm, invm, nm);

    encoder_wmma_kernel<<<gridNT, 128, PIPE_SMEM>>>(x_thesis, lin_W, lin_b, emb_t,
                                                    thesis_id, xt0);
    gather_rows_kernel<<<(nm * 16 + TB - 1) / TB, TB>>>(emb_m, mentor_id, xm0, nm);

    // ================= layer 0 =================
    // ym = xm0 @ Wl_mt0^T  (mentor rows, post-relu source not needed at L0)
    gemm64_kernel<false, false><<<gridNM, TB>>>(xm0, Wl_mt0, nullptr, ym, nm);
    // mentor agg: aggm = sum xt0[src] grouped by dst
    cudaMemsetAsync(aggm, 0, (size_t)nm * CH * sizeof(float));
    scatter_kernel<false><<<gridE16, TB>>>(xt0, edge_src, edge_dst, aggm, E);
    // mentor out (relu'd): xm1 = relu(aggm*invm@Wl_tm0^T + xm0@Wr_tm0^T + b_tm0)
    sage_kernel<true><<<gridNM, TB>>>(aggm, invm, xm0, Wl_tm0, Wr_tm0, b_tm0, xm1, nm);
    // thesis base (PRE-relu): xt1 = xt0@Wr_mt0^T + b_mt0
    gemm64_wmma_kernel<false><<<gridNT, 128, PIPE_SMEM>>>(xt0, Wr_mt0, b_mt0, xt1);
    // thesis agg fused: xt1[src] += ym[dst]*invt[src]
    scatter_scaled_kernel<<<gridE16, TB>>>(ym, edge_dst, edge_src, invt, xt1, E);

    // ================= layer 1 =================  (xt1 is pre-relu!)
    gemm64_kernel<false, false><<<gridNM, TB>>>(xm1, Wl_mt1, nullptr, ym, nm);
    cudaMemsetAsync(aggm, 0, (size_t)nm * CH * sizeof(float));
    scatter_kernel<true><<<gridE16, TB>>>(xt1, edge_src, edge_dst, aggm, E);
    sage_kernel<false><<<gridNM, TB>>>(aggm, invm, xm1, Wl_tm1, Wr_tm1, b_tm1, xm2, nm);
    gemm64_wmma_kernel<true><<<gridNT, 128, PIPE_SMEM>>>(xt1, Wr_mt1, b_mt1, xt2);
    scatter_scaled_kernel<<<gridE16, TB>>>(ym, edge_dst, edge_src, invt, xt2, E);

    // classifier
    edge_dot_kernel<<<gridEL16, TB>>>(xt2, xm2, el_src, el_dst, out, EL);
}

// round 16
// speedup vs baseline: 1.2652x; 1.0750x over previous
#include <cuda_runtime.h>
#include <cuda_bf16.h>
#include <mma.h>
#include <cstdint>
#include <cstddef>

using namespace nvcuda;

// Problem dims (fixed by dataset)
#define NTC 400000
#define NMC 40000
#define CH  64
#define FT  384

// ---------------- scratch (static __device__ — no allocations) ----------------
__device__ float g_xt0[(size_t)NTC * CH];
__device__ float g_xt1[(size_t)NTC * CH];
__device__ float g_xt2[(size_t)NTC * CH];
__device__ float g_xm0[(size_t)NMC * CH];
__device__ float g_xm1[(size_t)NMC * CH];
__device__ float g_xm2[(size_t)NMC * CH];
__device__ float g_aggm[(size_t)NMC * CH];
__device__ float g_ym[(size_t)NMC * CH];
__device__ float g_ym1[(size_t)NMC * CH];
__device__ int   g_cnt_t[NTC];
__device__ int   g_cnt_m[NMC];
__device__ float g_inv_t[NTC];
__device__ float g_inv_m[NMC];

// ---------------- packed f32x2 FMA ----------------
union F2U { float2 f; unsigned long long u; };
__device__ __forceinline__ float2 ffma2(float2 a, float2 b, float2 c) {
    F2U A, B, Cc, D;
    A.f = a; B.f = b; Cc.f = c;
    asm("fma.rn.f32x2 %0, %1, %2, %3;" : "=l"(D.u) : "l"(A.u), "l"(B.u), "l"(Cc.u));
    return D.f;
}

// ---------------- degree / recip ----------------
__global__ void degree_kernel(const int* __restrict__ esrc, const int* __restrict__ edst, int E) {
    int t = blockIdx.x * blockDim.x + threadIdx.x;
    if (t < E) {
        atomicAdd(&g_cnt_t[esrc[t]], 1);
        atomicAdd(&g_cnt_m[edst[t]], 1);
    }
}

__global__ void recip_kernel(const int* __restrict__ cnt, float* __restrict__ inv, int n) {
    int t = blockIdx.x * blockDim.x + threadIdx.x;
    if (t < n) inv[t] = 1.0f / fmaxf((float)cnt[t], 1.0f);
}

// ---------------- mentor encoder: x_m0 = emb_m[mentor_id] ----------------
__global__ void gather_rows_kernel(const float* __restrict__ src, const int* __restrict__ ids,
                                   float* __restrict__ out, int n) {
    int t = blockIdx.x * blockDim.x + threadIdx.x;
    int e = t >> 4;
    if (e >= n) return;
    int c4 = (t & 15) << 2;
    int id = __ldg(&ids[e]);
    float4 v = *reinterpret_cast<const float4*>(&src[(size_t)id * CH + c4]);
    *reinterpret_cast<float4*>(&out[(size_t)e * CH + c4]) = v;
}

// ---------------- edge scatter-add: agg[sidx[e]] += relu?(feat[gidx[e]]) -------
template <bool RELU_IN>
__global__ void scatter_kernel(const float* __restrict__ feat, const int* __restrict__ gidx,
                               const int* __restrict__ sidx, float* __restrict__ agg, int E) {
    int t = blockIdx.x * blockDim.x + threadIdx.x;
    int e = t >> 4;
    if (e >= E) return;
    int c4 = (t & 15) << 2;
    int s = __ldg(&gidx[e]);
    int d = __ldg(&sidx[e]);
    float4 v = *reinterpret_cast<const float4*>(&feat[(size_t)s * CH + c4]);
    if (RELU_IN) {
        v.x = fmaxf(v.x, 0.f); v.y = fmaxf(v.y, 0.f);
        v.z = fmaxf(v.z, 0.f); v.w = fmaxf(v.w, 0.f);
    }
    float* p = &agg[(size_t)d * CH + c4];
    asm volatile("red.global.add.v4.f32 [%0], {%1, %2, %3, %4};"
                 :: "l"(p), "f"(v.x), "f"(v.y), "f"(v.z), "f"(v.w) : "memory");
}

// ---------------- scaled edge scatter: out[src[e]] += ym[dst[e]] * inv[src[e]] --
__global__ void scatter_scaled_kernel(const float* __restrict__ ym,
                                      const int* __restrict__ edst,
                                      const int* __restrict__ esrc,
                                      const float* __restrict__ inv,
                                      float* __restrict__ out, int E) {
    int t = blockIdx.x * blockDim.x + threadIdx.x;
    int e = t >> 4;
    if (e >= E) return;
    int c4 = (t & 15) << 2;
    int d = __ldg(&edst[e]);
    int s = __ldg(&esrc[e]);
    float sc = __ldg(&inv[s]);
    float4 v = *reinterpret_cast<const float4*>(&ym[(size_t)d * CH + c4]);
    v.x *= sc; v.y *= sc; v.z *= sc; v.w *= sc;
    float* p = &out[(size_t)s * CH + c4];
    asm volatile("red.global.add.v4.f32 [%0], {%1, %2, %3, %4};"
                 :: "l"(p), "f"(v.x), "f"(v.y), "f"(v.z), "f"(v.w) : "memory");
}

// ============================================================================
// wmma bf16-split machinery — 4 warps, warp tile 32x64, double-buffered cv
// ============================================================================
#define AST 40   // smem k-stride (elements), mult of 8 for wmma ldm

struct CvBufs {
    __nv_bfloat16 Ahi[128][AST];
    __nv_bfloat16 Alo[128][AST];
    __nv_bfloat16 Bhi[64][AST];
    __nv_bfloat16 Blo[64][AST];
};

struct PipeSmem {
    union {
        CvBufs cv[2];
        float C[128][68];
    } u;
};
#define PIPE_SMEM ((int)sizeof(PipeSmem))

__device__ __forceinline__ void cvt_store_split(__nv_bfloat16* hi_p, __nv_bfloat16* lo_p,
                                                float4 v) {
    __nv_bfloat162 h01 = __floats2bfloat162_rn(v.x, v.y);
    __nv_bfloat162 h23 = __floats2bfloat162_rn(v.z, v.w);
    float2 f01 = __bfloat1622float2(h01);
    float2 f23 = __bfloat1622float2(h23);
    __nv_bfloat162 l01 = __floats2bfloat162_rn(v.x - f01.x, v.y - f01.y);
    __nv_bfloat162 l23 = __floats2bfloat162_rn(v.z - f23.x, v.w - f23.y);
    *reinterpret_cast<uint2*>(hi_p) = make_uint2(
        *reinterpret_cast<uint32_t*>(&h01), *reinterpret_cast<uint32_t*>(&h23));
    *reinterpret_cast<uint2*>(lo_p) = make_uint2(
        *reinterpret_cast<uint32_t*>(&l01), *reinterpret_cast<uint32_t*>(&l23));
}

// convert staged regs into cv buffer (A: 8 f4/thread, B: 4 f4/thread, 128 thr)
__device__ __forceinline__ void convert_chunk(CvBufs& cv, int tid,
                                              const float4 (&ar)[8], const float4 (&wr)[4]) {
#pragma unroll
    for (int j = 0; j < 8; j++) {
        int idx = tid + 128 * j;
        int r = idx >> 3, cq = (idx & 7) << 2;
        cvt_store_split(&cv.Ahi[r][cq], &cv.Alo[r][cq], ar[j]);
    }
#pragma unroll
    for (int j = 0; j < 4; j++) {
        int idx = tid + 128 * j;
        int r = idx >> 3, cq = (idx & 7) << 2;
        cvt_store_split(&cv.Bhi[r][cq], &cv.Blo[r][cq], wr[j]);
    }
}

// warp computes 32x64 tile: 2x4 accumulators, 3 split terms per 16-k step
__device__ __forceinline__ void wmma_chunk_mma4(
    CvBufs& cv, int warp_r,
    wmma::fragment<wmma::accumulator, 16, 16, 16, float> (&acc)[2][4]) {
#pragma unroll
    for (int kk = 0; kk < 32; kk += 16) {
        wmma::fragment<wmma::matrix_a, 16, 16, 16, __nv_bfloat16, wmma::row_major> ah[2], al[2];
#pragma unroll
        for (int i = 0; i < 2; i++) {
            wmma::load_matrix_sync(ah[i], &cv.Ahi[warp_r * 32 + i * 16][kk], AST);
            wmma::load_matrix_sync(al[i], &cv.Alo[warp_r * 32 + i * 16][kk], AST);
        }
#pragma unroll
        for (int j = 0; j < 4; j++) {
            wmma::fragment<wmma::matrix_b, 16, 16, 16, __nv_bfloat16, wmma::col_major> bh, bl;
            wmma::load_matrix_sync(bh, &cv.Bhi[j * 16][kk], AST);
            wmma::load_matrix_sync(bl, &cv.Blo[j * 16][kk], AST);
#pragma unroll
            for (int i = 0; i < 2; i++) {
                wmma::mma_sync(acc[i][j], ah[i], bh, acc[i][j]);
                wmma::mma_sync(acc[i][j], ah[i], bl, acc[i][j]);
                wmma::mma_sync(acc[i][j], al[i], bh, acc[i][j]);
            }
        }
    }
}

__device__ __forceinline__ float4 relu4(float4 v) {
    v.x = fmaxf(v.x, 0.f); v.y = fmaxf(v.y, 0.f);
    v.z = fmaxf(v.z, 0.f); v.w = fmaxf(v.w, 0.f);
    return v;
}

// ============================================================================
// Pipelined wmma encoder (128 thr): out[128,64] = X[128,384]@W[64,384]^T+b+emb
// ============================================================================
__global__ __launch_bounds__(128, 3)
void encoder_wmma_kernel(const float* __restrict__ X, const float* __restrict__ W,
                         const float* __restrict__ bias, const float* __restrict__ emb,
                         const int* __restrict__ ids, float* __restrict__ out) {
    extern __shared__ char smraw[];
    PipeSmem& sm = *reinterpret_cast<PipeSmem*>(smraw);
    int tid = threadIdx.x;
    int warp_r = tid >> 5;
    int row0 = blockIdx.x * 128;

    wmma::fragment<wmma::accumulator, 16, 16, 16, float> acc[2][4];
#pragma unroll
    for (int i = 0; i < 2; i++)
#pragma unroll
        for (int j = 0; j < 4; j++) wmma::fill_fragment(acc[i][j], 0.0f);

    int a_r = tid >> 3;
    int cq  = (tid & 7) << 2;
    float4 ar[8], wr[4];

#pragma unroll
    for (int j = 0; j < 8; j++)
        ar[j] = *reinterpret_cast<const float4*>(&X[(size_t)(row0 + a_r + 16 * j) * FT + cq]);
#pragma unroll
    for (int j = 0; j < 4; j++)
        wr[j] = *reinterpret_cast<const float4*>(&W[(size_t)(a_r + 16 * j) * FT + cq]);
    convert_chunk(sm.u.cv[0], tid, ar, wr);
    __syncthreads();

    const int NC = FT / 32;  // 12
    for (int ch = 0; ch < NC; ch++) {
        int buf = ch & 1;
        bool more = (ch + 1 < NC);
        if (more) {
            int kt = (ch + 1) * 32;
#pragma unroll
            for (int j = 0; j < 8; j++)
                ar[j] = *reinterpret_cast<const float4*>(
                    &X[(size_t)(row0 + a_r + 16 * j) * FT + kt + cq]);
#pragma unroll
            for (int j = 0; j < 4; j++)
                wr[j] = *reinterpret_cast<const float4*>(
                    &W[(size_t)(a_r + 16 * j) * FT + kt + cq]);
        }
        wmma_chunk_mma4(sm.u.cv[buf], warp_r, acc);
        if (more) convert_chunk(sm.u.cv[buf ^ 1], tid, ar, wr);
        __syncthreads();
    }

#pragma unroll
    for (int i = 0; i < 2; i++)
#pragma unroll
        for (int j = 0; j < 4; j++)
            wmma::store_matrix_sync(&sm.u.C[warp_r * 32 + i * 16][j * 16],
                                    acc[i][j], 68, wmma::mem_row_major);
    __syncthreads();

    int tx = tid & 15, ty = tid >> 4;
    int c4 = tx * 4;
    float4 bv = *reinterpret_cast<const float4*>(&bias[c4]);
#pragma unroll
    for (int p = 0; p < 16; p++) {
        int r = ty + p * 8;
        int nid = __ldg(&ids[row0 + r]);
        float4 ev = *reinterpret_cast<const float4*>(&emb[(size_t)nid * CH + c4]);
        float4 o;
        o.x = sm.u.C[r][c4 + 0] + bv.x + ev.x;
        o.y = sm.u.C[r][c4 + 1] + bv.y + ev.y;
        o.z = sm.u.C[r][c4 + 2] + bv.z + ev.z;
        o.w = sm.u.C[r][c4 + 3] + bv.w + ev.w;
        *reinterpret_cast<float4*>(&out[(size_t)(row0 + r) * CH + c4]) = o;
    }
}

// ============================================================================
// Pipelined wmma thesis base GEMM (128 thr):
// out[128,64] = relu_in?(X)[128,64]@W[64,64]^T + b      (agg added later by
// scatter_scaled; NO output relu — readers apply it)
// ============================================================================
template <bool RELU_IN>
__global__ __launch_bounds__(128, 3)
void gemm64_wmma_kernel(const float* __restrict__ X, const float* __restrict__ W,
                        const float* __restrict__ bias, float* __restrict__ out) {
    extern __shared__ char smraw[];
    PipeSmem& sm = *reinterpret_cast<PipeSmem*>(smraw);
    int tid = threadIdx.x;
    int warp_r = tid >> 5;
    int row0 = blockIdx.x * 128;

    wmma::fragment<wmma::accumulator, 16, 16, 16, float> acc[2][4];
#pragma unroll
    for (int i = 0; i < 2; i++)
#pragma unroll
        for (int j = 0; j < 4; j++) wmma::fill_fragment(acc[i][j], 0.0f);

    int a_r = tid >> 3;
    int cq  = (tid & 7) << 2;
    float4 ar[8], wr[4];

#pragma unroll
    for (int j = 0; j < 8; j++) {
        ar[j] = *reinterpret_cast<const float4*>(&X[(size_t)(row0 + a_r + 16 * j) * CH + cq]);
        if (RELU_IN) ar[j] = relu4(ar[j]);
    }
#pragma unroll
    for (int j = 0; j < 4; j++)
        wr[j] = *reinterpret_cast<const float4*>(&W[(size_t)(a_r + 16 * j) * CH + cq]);
    convert_chunk(sm.u.cv[0], tid, ar, wr);
    __syncthreads();

#pragma unroll
    for (int j = 0; j < 8; j++) {
        ar[j] = *reinterpret_cast<const float4*>(&X[(size_t)(row0 + a_r + 16 * j) * CH + 32 + cq]);
        if (RELU_IN) ar[j] = relu4(ar[j]);
    }
#pragma unroll
    for (int j = 0; j < 4; j++)
        wr[j] = *reinterpret_cast<const float4*>(&W[(size_t)(a_r + 16 * j) * CH + 32 + cq]);

    wmma_chunk_mma4(sm.u.cv[0], warp_r, acc);
    convert_chunk(sm.u.cv[1], tid, ar, wr);
    __syncthreads();
    wmma_chunk_mma4(sm.u.cv[1], warp_r, acc);
    __syncthreads();

#pragma unroll
    for (int i = 0; i < 2; i++)
#pragma unroll
        for (int j = 0; j < 4; j++)
            wmma::store_matrix_sync(&sm.u.C[warp_r * 32 + i * 16][j * 16],
                                    acc[i][j], 68, wmma::mem_row_major);
    __syncthreads();

    int tx = tid & 15, ty = tid >> 4;
    int c4 = tx * 4;
    float4 bv = *reinterpret_cast<const float4*>(&bias[c4]);
#pragma unroll
    for (int p = 0; p < 16; p++) {
        int r = ty + p * 8;
        int gr = row0 + r;
        float4 o;
        o.x = sm.u.C[r][c4 + 0] + bv.x;
        o.y = sm.u.C[r][c4 + 1] + bv.y;
        o.z = sm.u.C[r][c4 + 2] + bv.z;
        o.w = sm.u.C[r][c4 + 3] + bv.w;
        *reinterpret_cast<float4*>(&out[(size_t)gr * CH + c4]) = o;
    }
}

// ---------------- K=64 FFMA2 GEMM (mentor ym, R4 proven body) ------------------
template <bool RELU, bool BIAS>
__global__ __launch_bounds__(256)
void gemm64_kernel(const float* __restrict__ X, const float* __restrict__ W,
                   const float* __restrict__ bias, float* __restrict__ out, int M) {
    __shared__ float As[32][132];
    __shared__ float Ws[32][68];
    int tid = threadIdx.x;
    int tx = tid & 15, ty = tid >> 4;
    int row0 = blockIdx.x * 128;

    float2 acc[4][4];
#pragma unroll
    for (int i = 0; i < 4; i++)
#pragma unroll
        for (int j = 0; j < 4; j++) acc[i][j] = make_float2(0.f, 0.f);

    for (int kt = 0; kt < CH; kt += 32) {
#pragma unroll
        for (int i = 0; i < 4; i++) {
            int idx = tid + 256 * i;
            int r = idx >> 3;
            int kq = (idx & 7) << 2;
            int grow = row0 + r;
            float4 v = make_float4(0.f, 0.f, 0.f, 0.f);
            if (grow < M)
                v = *reinterpret_cast<const float4*>(&X[(size_t)grow * CH + kt + kq]);
            As[kq + 0][r] = v.x; As[kq + 1][r] = v.y;
            As[kq + 2][r] = v.z; As[kq + 3][r] = v.w;
        }
#pragma unroll
        for (int i = 0; i < 2; i++) {
            int idx = tid + 256 * i;
            int c = idx >> 3;
            int kq = (idx & 7) << 2;
            float4 v = *reinterpret_cast<const float4*>(&W[(size_t)c * CH + kt + kq]);
            Ws[kq + 0][c] = v.x; Ws[kq + 1][c] = v.y;
            Ws[kq + 2][c] = v.z; Ws[kq + 3][c] = v.w;
        }
        __syncthreads();
#pragma unroll
        for (int k = 0; k < 32; k++) {
            float4 a0 = *reinterpret_cast<const float4*>(&As[k][ty * 8]);
            float4 a1 = *reinterpret_cast<const float4*>(&As[k][ty * 8 + 4]);
            float4 w  = *reinterpret_cast<const float4*>(&Ws[k][tx * 4]);
            float2 ap[4] = { {a0.x, a0.y}, {a0.z, a0.w}, {a1.x, a1.y}, {a1.z, a1.w} };
            float2 wd[4] = { {w.x, w.x}, {w.y, w.y}, {w.z, w.z}, {w.w, w.w} };
#pragma unroll
            for (int rp = 0; rp < 4; rp++)
#pragma unroll
                for (int j = 0; j < 4; j++)
                    acc[rp][j] = ffma2(ap[rp], wd[j], acc[rp][j]);
        }
        __syncthreads();
    }

    float4 bv = make_float4(0.f, 0.f, 0.f, 0.f);
    if (BIAS) bv = *reinterpret_cast<const float4*>(&bias[tx * 4]);
#pragma unroll
    for (int rp = 0; rp < 4; rp++) {
#pragma unroll
        for (int s = 0; s < 2; s++) {
            int r = row0 + ty * 8 + rp * 2 + s;
            if (r < M) {
                float4 o;
                o.x = (s ? acc[rp][0].y : acc[rp][0].x) + bv.x;
                o.y = (s ? acc[rp][1].y : acc[rp][1].x) + bv.y;
                o.z = (s ? acc[rp][2].y : acc[rp][2].x) + bv.z;
                o.w = (s ? acc[rp][3].y : acc[rp][3].x) + bv.w;
                if (RELU) {
                    o.x = fmaxf(o.x, 0.f); o.y = fmaxf(o.y, 0.f);
                    o.z = fmaxf(o.z, 0.f); o.w = fmaxf(o.w, 0.f);
                }
                *reinterpret_cast<float4*>(&out[(size_t)r * CH + tx * 4]) = o;
            }
        }
    }
}

// ---------------- mentor SAGE layer GEMM (K=128, R4 proven body) ---------------
template <bool RELU>
__global__ __launch_bounds__(256)
void sage_kernel(const float* __restrict__ Agg, const float* __restrict__ inv,
                 const float* __restrict__ Xs,
                 const float* __restrict__ Wl, const float* __restrict__ Wr,
                 const float* __restrict__ bias, float* __restrict__ out, int M) {
    __shared__ float As[32][132];
    __shared__ float Ws[32][68];
    int tid = threadIdx.x;
    int tx = tid & 15, ty = tid >> 4;
    int row0 = blockIdx.x * 128;

    float2 acc[4][4];
#pragma unroll
    for (int i = 0; i < 4; i++)
#pragma unroll
        for (int j = 0; j < 4; j++) acc[i][j] = make_float2(0.f, 0.f);

    for (int tt = 0; tt < 4; tt++) {
        const float* A  = (tt < 2) ? Agg : Xs;
        const float* Wp = (tt < 2) ? Wl  : Wr;
        bool do_scale = (tt < 2);
        int kt = (tt & 1) * 32;
#pragma unroll
        for (int i = 0; i < 4; i++) {
            int idx = tid + 256 * i;
            int r = idx >> 3;
            int kq = (idx & 7) << 2;
            int grow = row0 + r;
            float4 v = make_float4(0.f, 0.f, 0.f, 0.f);
            if (grow < M) {
                v = *reinterpret_cast<const float4*>(&A[(size_t)grow * CH + kt + kq]);
                if (do_scale) {
                    float sc = __ldg(&inv[grow]);
                    v.x *= sc; v.y *= sc; v.z *= sc; v.w *= sc;
                }
            }
            As[kq + 0][r] = v.x; As[kq + 1][r] = v.y;
            As[kq + 2][r] = v.z; As[kq + 3][r] = v.w;
        }
#pragma unroll
        for (int i = 0; i < 2; i++) {
            int idx = tid + 256 * i;
            int c = idx >> 3;
            int kq = (idx & 7) << 2;
            float4 v = *reinterpret_cast<const float4*>(&Wp[(size_t)c * CH + kt + kq]);
            Ws[kq + 0][c] = v.x; Ws[kq + 1][c] = v.y;
            Ws[kq + 2][c] = v.z; Ws[kq + 3][c] = v.w;
        }
        __syncthreads();
#pragma unroll
        for (int k = 0; k < 32; k++) {
            float4 a0 = *reinterpret_cast<const float4*>(&As[k][ty * 8]);
            float4 a1 = *reinterpret_cast<const float4*>(&As[k][ty * 8 + 4]);
            float4 w  = *reinterpret_cast<const float4*>(&Ws[k][tx * 4]);
            float2 ap[4] = { {a0.x, a0.y}, {a0.z, a0.w}, {a1.x, a1.y}, {a1.z, a1.w} };
            float2 wd[4] = { {w.x, w.x}, {w.y, w.y}, {w.z, w.z}, {w.w, w.w} };
#pragma unroll
            for (int rp = 0; rp < 4; rp++)
#pragma unroll
                for (int j = 0; j < 4; j++)
                    acc[rp][j] = ffma2(ap[rp], wd[j], acc[rp][j]);
        }
        __syncthreads();
    }

    float4 bv = *reinterpret_cast<const float4*>(&bias[tx * 4]);
#pragma unroll
    for (int rp = 0; rp < 4; rp++) {
#pragma unroll
        for (int s = 0; s < 2; s++) {
            int r = row0 + ty * 8 + rp * 2 + s;
            if (r < M) {
                float4 o;
                o.x = (s ? acc[rp][0].y : acc[rp][0].x) + bv.x;
                o.y = (s ? acc[rp][1].y : acc[rp][1].x) + bv.y;
                o.z = (s ? acc[rp][2].y : acc[rp][2].x) + bv.z;
                o.w = (s ? acc[rp][3].y : acc[rp][3].x) + bv.w;
                if (RELU) {
                    o.x = fmaxf(o.x, 0.f); o.y = fmaxf(o.y, 0.f);
                    o.z = fmaxf(o.z, 0.f); o.w = fmaxf(o.w, 0.f);
                }
                *reinterpret_cast<float4*>(&out[(size_t)r * CH + tx * 4]) = o;
            }
        }
    }
}

// ---------------- edge dot-product classifier --------------------------------
__global__ void edge_dot_kernel(const float* __restrict__ xt, const float* __restrict__ xm,
                                const int* __restrict__ es, const int* __restrict__ ed,
                                float* __restrict__ out, int E) {
    int t = blockIdx.x * blockDim.x + threadIdx.x;
    int e = t >> 4;
    if (e >= E) return;
    int c4 = (t & 15) << 2;
    int s = __ldg(&es[e]);
    int d = __ldg(&ed[e]);
    float4 a = *reinterpret_cast<const float4*>(&xt[(size_t)s * CH + c4]);
    float4 b = *reinterpret_cast<const float4*>(&xm[(size_t)d * CH + c4]);
    float p = a.x * b.x + a.y * b.y + a.z * b.z + a.w * b.w;
    p += __shfl_down_sync(0xffffffffu, p, 8);
    p += __shfl_down_sync(0xffffffffu, p, 4);
    p += __shfl_down_sync(0xffffffffu, p, 2);
    p += __shfl_down_sync(0xffffffffu, p, 1);
    if ((t & 15) == 0) out[e] = p;
}

// ---------------- launch -----------------------------------------------------
extern "C" void kernel_launch(void* const* d_in, const int* in_sizes, int n_in,
                              void* d_out, int out_size) {
    const float* x_thesis  = (const float*)d_in[0];
    const int*   thesis_id = (const int*)d_in[1];
    const int*   mentor_id = (const int*)d_in[2];
    const int*   edge_src  = (const int*)d_in[3];
    const int*   edge_dst  = (const int*)d_in[4];
    const int*   el_src    = (const int*)d_in[5];
    const int*   el_dst    = (const int*)d_in[6];
    const float* lin_W     = (const float*)d_in[7];
    const float* lin_b     = (const float*)d_in[8];
    const float* emb_t     = (const float*)d_in[9];
    const float* emb_m     = (const float*)d_in[10];
    const float* Wl_tm0    = (const float*)d_in[11];
    const float* Wr_tm0    = (const float*)d_in[12];
    const float* b_tm0     = (const float*)d_in[13];
    const float* Wl_mt0    = (const float*)d_in[14];
    const float* Wr_mt0    = (const float*)d_in[15];
    const float* b_mt0     = (const float*)d_in[16];
    const float* Wl_tm1    = (const float*)d_in[17];
    const float* Wr_tm1    = (const float*)d_in[18];
    const float* b_tm1     = (const float*)d_in[19];
    const float* Wl_mt1    = (const float*)d_in[20];
    const float* Wr_mt1    = (const float*)d_in[21];
    const float* b_mt1     = (const float*)d_in[22];
    float* out = (float*)d_out;

    int nt = in_sizes[1];
    int nm = in_sizes[2];
    int E  = in_sizes[3];
    int EL = in_sizes[5];

    void *p_xt0, *p_xt1, *p_xt2, *p_xm0, *p_xm1, *p_xm2, *p_aggm, *p_ym, *p_ym1;
    void *p_cntt, *p_cntm, *p_invt, *p_invm;
    cudaGetSymbolAddress(&p_xt0, g_xt0);   cudaGetSymbolAddress(&p_xt1, g_xt1);
    cudaGetSymbolAddress(&p_xt2, g_xt2);
    cudaGetSymbolAddress(&p_xm0, g_xm0);   cudaGetSymbolAddress(&p_xm1, g_xm1);
    cudaGetSymbolAddress(&p_xm2, g_xm2);   cudaGetSymbolAddress(&p_aggm, g_aggm);
    cudaGetSymbolAddress(&p_ym, g_ym);     cudaGetSymbolAddress(&p_ym1, g_ym1);
    cudaGetSymbolAddress(&p_cntt, g_cnt_t); cudaGetSymbolAddress(&p_cntm, g_cnt_m);
    cudaGetSymbolAddress(&p_invt, g_inv_t); cudaGetSymbolAddress(&p_invm, g_inv_m);

    float* xt0 = (float*)p_xt0; float* xt1 = (float*)p_xt1; float* xt2 = (float*)p_xt2;
    float* xm0 = (float*)p_xm0; float* xm1 = (float*)p_xm1; float* xm2 = (float*)p_xm2;
    float* aggm = (float*)p_aggm; float* ym0 = (float*)p_ym; float* ym1 = (float*)p_ym1;
    int* cntt = (int*)p_cntt; int* cntm = (int*)p_cntm;
    float* invt = (float*)p_invt; float* invm = (float*)p_invm;

    // ---- one-time setup (first call is the non-captured correctness run) ----
    static bool s_init = false;
    static cudaStream_t sB;
    static cudaEvent_t evFork, evEnc, evYm0, evSS0, evYm1, evXm2;
    if (!s_init) {
        cudaFuncSetAttribute(encoder_wmma_kernel,
                             cudaFuncAttributeMaxDynamicSharedMemorySize, PIPE_SMEM);
        cudaFuncSetAttribute(gemm64_wmma_kernel<true>,
                             cudaFuncAttributeMaxDynamicSharedMemorySize, PIPE_SMEM);
        cudaFuncSetAttribute(gemm64_wmma_kernel<false>,
                             cudaFuncAttributeMaxDynamicSharedMemorySize, PIPE_SMEM);
        cudaStreamCreateWithFlags(&sB, cudaStreamNonBlocking);
        cudaEventCreateWithFlags(&evFork, cudaEventDisableTiming);
        cudaEventCreateWithFlags(&evEnc,  cudaEventDisableTiming);
        cudaEventCreateWithFlags(&evYm0,  cudaEventDisableTiming);
        cudaEventCreateWithFlags(&evSS0,  cudaEventDisableTiming);
        cudaEventCreateWithFlags(&evYm1,  cudaEventDisableTiming);
        cudaEventCreateWithFlags(&evXm2,  cudaEventDisableTiming);
        s_init = true;
    }

    const int TB = 256;
    int gridE16  = (E * 16 + TB - 1) / TB;
    int gridEL16 = (EL * 16 + TB - 1) / TB;
    int gridNT   = (nt + 127) / 128;
    int gridNM   = (nm + 127) / 128;

    // ---- fork: stream B handles the mentor-side chain ----
    cudaEventRecord(evFork, 0);
    cudaStreamWaitEvent(sB, evFork, 0);

    // stream B prologue (independent of encoder).
    // CRITICAL: zero the degree counters every call — degree_kernel accumulates
    // atomically and the graph is replayed many times (R15 failure).
    cudaMemsetAsync(cntt, 0, (size_t)nt * sizeof(int), sB);
    cudaMemsetAsync(cntm, 0, (size_t)nm * sizeof(int), sB);
    degree_kernel<<<(E + TB - 1) / TB, TB, 0, sB>>>(edge_src, edge_dst, E);
    recip_kernel<<<(nt + TB - 1) / TB, TB, 0, sB>>>(cntt, invt, nt);
    recip_kernel<<<(nm + TB - 1) / TB, TB, 0, sB>>>(cntm, invm, nm);
    gather_rows_kernel<<<(nm * 16 + TB - 1) / TB, TB, 0, sB>>>(emb_m, mentor_id, xm0, nm);
    gemm64_kernel<false, false><<<gridNM, TB, 0, sB>>>(xm0, Wl_mt0, nullptr, ym0, nm);
    cudaEventRecord(evYm0, sB);
    cudaMemsetAsync(aggm, 0, (size_t)nm * CH * sizeof(float), sB);

    // stream 0: encoder
    encoder_wmma_kernel<<<gridNT, 128, PIPE_SMEM>>>(x_thesis, lin_W, lin_b, emb_t,
                                                    thesis_id, xt0);
    cudaEventRecord(evEnc, 0);

    // ===== stream B: mentor L0 (needs xt0) + ym1 =====
    cudaStreamWaitEvent(sB, evEnc, 0);
    scatter_kernel<false><<<gridE16, TB, 0, sB>>>(xt0, edge_src, edge_dst, aggm, E);
    sage_kernel<true><<<gridNM, TB, 0, sB>>>(aggm, invm, xm0, Wl_tm0, Wr_tm0, b_tm0, xm1, nm);
    gemm64_kernel<false, false><<<gridNM, TB, 0, sB>>>(xm1, Wl_mt1, nullptr, ym1, nm);
    cudaEventRecord(evYm1, sB);
    cudaMemsetAsync(aggm, 0, (size_t)nm * CH * sizeof(float), sB);

    // ===== stream 0: thesis L0 =====
    gemm64_wmma_kernel<false><<<gridNT, 128, PIPE_SMEM>>>(xt0, Wr_mt0, b_mt0, xt1);
    cudaStreamWaitEvent(0, evYm0, 0);
    scatter_scaled_kernel<<<gridE16, TB>>>(ym0, edge_dst, edge_src, invt, xt1, E);
    cudaEventRecord(evSS0, 0);

    // ===== stream B: mentor L1 (needs xt1 complete) =====
    cudaStreamWaitEvent(sB, evSS0, 0);
    scatter_kernel<true><<<gridE16, TB, 0, sB>>>(xt1, edge_src, edge_dst, aggm, E);
    sage_kernel<false><<<gridNM, TB, 0, sB>>>(aggm, invm, xm1, Wl_tm1, Wr_tm1, b_tm1, xm2, nm);
    cudaEventRecord(evXm2, sB);

    // ===== stream 0: thesis L1 + classifier =====
    gemm64_wmma_kernel<true><<<gridNT, 128, PIPE_SMEM>>>(xt1, Wr_mt1, b_mt1, xt2);
    cudaStreamWaitEvent(0, evYm1, 0);
    scatter_scaled_kernel<<<gridE16, TB>>>(ym1, edge_dst, edge_src, invt, xt2, E);
    cudaStreamWaitEvent(0, evXm2, 0);
    edge_dot_kernel<<<gridEL16, TB>>>(xt2, xm2, el_src, el_dst, out, EL);
}